// round 9
// baseline (speedup 1.0000x reference)
#include <cuda_runtime.h>
#include <cstdint>
#include <cstddef>

#define N_ROWS   262144
#define DDIM     64
#define QSTAGES  8
#define KCODES   1024
#define TM       128
#define TN       128
#define NTHREADS 256
#define RPAD2    256            // duplicated rT row stride (floats) = 2*TM
#define CPAD     128            // cbT row stride (floats)

// shared memory layout (float units)
#define OFF_RT   0
#define OFF_CB   (OFF_RT + DDIM * RPAD2)         // 16384 (single-buffered cb)
#define OFF_HN   (OFF_CB + DDIM * CPAD)          // 24576
#define OFF_IDX  (OFF_HN + KCODES)               // 25600 (TM ints)
#define SMEM_FLOATS (OFF_IDX + TM)               // 25728
#define SMEM_BYTES  (SMEM_FLOATS * 4)            // 102,912 B (x2 CTAs = 206KB/SM)

// hn[q][k] = XLA-emulated fp32 sum(cb*cb) (warp-tree reduction)
__device__ float g_hn[QSTAGES * KCODES];
// scratch for quantized accumulation if harness gives no qz region
__device__ float g_qscratch[(size_t)N_ROWS * DDIM];

// ---------------- packed f32x2 helpers ----------------
__device__ __forceinline__ void ffma2(unsigned long long& acc,
                                      unsigned long long a,
                                      unsigned long long b) {
    asm("fma.rn.f32x2 %0, %1, %2, %0;" : "+l"(acc) : "l"(a), "l"(b));
}
__device__ __forceinline__ float2 unpack2(unsigned long long p) {
    float2 r;
    asm("mov.b64 {%0, %1}, %2;" : "=f"(r.x), "=f"(r.y) : "l"(p));
    return r;
}
// store {v, v} (duplicated pair) to smem with one STS.64, no MOVs
__device__ __forceinline__ void sts_dup(float* addr, float v) {
    asm volatile("st.shared.v2.f32 [%0], {%1, %1};"
                 :: "r"((uint32_t)__cvta_generic_to_shared(addr)), "f"(v));
}

// ---------------- codebook norms: emulate XLA row-reduction ----------------
__global__ void hn_kernel(const float* __restrict__ cb) {
    int warp = (blockIdx.x * blockDim.x + threadIdx.x) >> 5;
    int lane = threadIdx.x & 31;
    if (warp < QSTAGES * KCODES) {
        const float* row = cb + (size_t)warp * DDIM;
        float c0 = row[lane];
        float c1 = row[lane + 32];
        float acc = __fmaf_rn(c0, c0, 0.0f);
        acc = __fmaf_rn(c1, c1, acc);
#pragma unroll
        for (int off = 16; off > 0; off >>= 1) {
            float sh = __shfl_down_sync(0xffffffffu, acc, off);
            acc = acc + sh;
        }
        if (lane == 0) g_hn[warp] = acc;
    }
}

// ---- chunk staging: gmem -> transposed smem (conflict-free, 256 thr) ----
__device__ __forceinline__ void stage_chunk(const float* __restrict__ cbq,
                                            int c, float* __restrict__ buf,
                                            int tid) {
    int klocal = tid & 127;            // consecutive lanes -> consecutive cols
    int dbase = (tid >> 7) << 5;       // 0 or 32
    const float4* p = reinterpret_cast<const float4*>(
        cbq + ((size_t)(c * TN + klocal)) * DDIM + dbase);
#pragma unroll
    for (int j = 0; j < 8; j++) {
        float4 v = p[j];
        int dd = dbase + (j << 2);
        buf[(dd + 0) * CPAD + klocal] = v.x;
        buf[(dd + 1) * CPAD + klocal] = v.y;
        buf[(dd + 2) * CPAD + klocal] = v.z;
        buf[(dd + 3) * CPAD + klocal] = v.w;
    }
}

// ---------------- main fused RVQ kernel ----------------
__global__ void __launch_bounds__(NTHREADS, 2)
rvq_kernel(const float* __restrict__ x, const float* __restrict__ cb,
           float* __restrict__ qbuf, float* __restrict__ enc_f,
           int* __restrict__ enc_i) {
    extern __shared__ float smem[];
    float* s_rT  = smem + OFF_RT;      // duplicated residual: pair {r,r} per row
    float* s_cbT = smem + OFF_CB;
    float* s_hn  = smem + OFF_HN;
    int*   s_idx = reinterpret_cast<int*>(smem + OFF_IDX);

    const int tid = threadIdx.x;
    const int tx = tid & 15;           // 16 col-groups of 8
    const int ty = tid >> 4;           // 16 row-groups of 8
    const int row_base = blockIdx.x * TM;
    const int n2 = tid >> 1;           // update/init mapping: row
    const int dh = (tid & 1) << 5;     // and 32-d half

    // ---- init: rT = x (transposed, duplicated pairs) ----
    {
        const float4* xp = reinterpret_cast<const float4*>(
            x + (size_t)(row_base + n2) * DDIM + dh);
#pragma unroll
        for (int j = 0; j < 8; j++) {
            float4 v = xp[j];
            int dd = dh + (j << 2);
            sts_dup(s_rT + (dd + 0) * RPAD2 + (n2 << 1), v.x);
            sts_dup(s_rT + (dd + 1) * RPAD2 + (n2 << 1), v.y);
            sts_dup(s_rT + (dd + 2) * RPAD2 + (n2 << 1), v.z);
            sts_dup(s_rT + (dd + 3) * RPAD2 + (n2 << 1), v.w);
        }
    }

    for (int q = 0; q < QSTAGES; q++) {
        const float* cbq = cb + (size_t)q * (KCODES * DDIM);

#pragma unroll
        for (int i = 0; i < KCODES / NTHREADS; i++)
            s_hn[tid + i * NTHREADS] = g_hn[q * KCODES + tid + i * NTHREADS];
        __syncthreads();   // rT updates + hn visible; prev-stage cb reads done

        float bestd[8];
        int besti[8];
#pragma unroll
        for (int i = 0; i < 8; i++) { bestd[i] = 3.0e38f; besti[i] = 0x7fffffff; }

        for (int c = 0; c < KCODES / TN; c++) {
            stage_chunk(cbq, c, s_cbT, tid);
            __syncthreads();

            unsigned long long acc[8][4];
#pragma unroll
            for (int i = 0; i < 8; i++)
#pragma unroll
                for (int j = 0; j < 4; j++) acc[i][j] = 0ULL;

            const float* arow = s_rT + (ty << 4);
            const float* brow = s_cbT + (tx << 2);

            // s = sum_d r[d]*c[d]: fma, d ascending, single accumulator per
            // scalar output (per packed half) — bit-identical to SGEMM k-loop.
#pragma unroll 4
            for (int d = 0; d < DDIM; d++) {
                ulonglong2 a01 = *reinterpret_cast<const ulonglong2*>(arow);
                ulonglong2 a23 = *reinterpret_cast<const ulonglong2*>(arow + 4);
                ulonglong2 a45 = *reinterpret_cast<const ulonglong2*>(arow + 8);
                ulonglong2 a67 = *reinterpret_cast<const ulonglong2*>(arow + 12);
                ulonglong2 b0 = *reinterpret_cast<const ulonglong2*>(brow);
                ulonglong2 b1 = *reinterpret_cast<const ulonglong2*>(brow + 64);
                unsigned long long ap[8] = {a01.x, a01.y, a23.x, a23.y,
                                            a45.x, a45.y, a67.x, a67.y};
#pragma unroll
                for (int i = 0; i < 8; i++) {
                    ffma2(acc[i][0], ap[i], b0.x);
                    ffma2(acc[i][1], ap[i], b0.y);
                    ffma2(acc[i][2], ap[i], b1.x);
                    ffma2(acc[i][3], ap[i], b1.y);
                }
                arow += RPAD2;
                brow += CPAD;
            }

            // epilogue: d = fma(-2, s, hn); running strict min (cols ascending)
            {
                int cb1 = c * TN + (tx << 2);
                float4 h0 = *reinterpret_cast<const float4*>(s_hn + cb1);
                float4 h1 = *reinterpret_cast<const float4*>(s_hn + cb1 + 64);
                float hh[8] = {h0.x, h0.y, h0.z, h0.w, h1.x, h1.y, h1.z, h1.w};
#pragma unroll
                for (int i = 0; i < 8; i++) {
#pragma unroll
                    for (int j = 0; j < 4; j++) {
                        float2 v = unpack2(acc[i][j]);
                        int c0 = cb1 + ((j >> 1) ? 64 : 0) + ((j & 1) << 1);
                        float d0v = __fmaf_rn(-2.0f, v.x,
                                              hh[(j >> 1) * 4 + ((j & 1) << 1)]);
                        float d1v = __fmaf_rn(-2.0f, v.y,
                                              hh[(j >> 1) * 4 + ((j & 1) << 1) + 1]);
                        if (d0v < bestd[i]) { bestd[i] = d0v; besti[i] = c0; }
                        if (d1v < bestd[i]) { bestd[i] = d1v; besti[i] = c0 + 1; }
                    }
                }
            }
            __syncthreads();   // compute done before next chunk overwrites cb
        }

        // cross-lane argmin merge over 16 tx lanes (lexicographic (d, idx))
#pragma unroll
        for (int i = 0; i < 8; i++) {
#pragma unroll
            for (int off = 8; off > 0; off >>= 1) {
                float ov = __shfl_xor_sync(0xffffffffu, bestd[i], off);
                int oi = __shfl_xor_sync(0xffffffffu, besti[i], off);
                if (ov < bestd[i] || (ov == bestd[i] && oi < besti[i])) {
                    bestd[i] = ov;
                    besti[i] = oi;
                }
            }
        }
        if (tx == 0) {
#pragma unroll
            for (int i = 0; i < 8; i++) {
                int row = (ty << 3) + i;
                int id = besti[i];
                s_idx[row] = id;
                size_t e = (size_t)(row_base + row) * QSTAGES + q;
                if (enc_f) enc_f[e] = (float)id;
                if (enc_i) enc_i[e] = id;
            }
        }
        __syncthreads();

        // ---- update: q += cb[idx] (fp32, ref order; q lives in gmem);
        //      r = x - q (written as duplicated pairs) ----
        {
            int id = s_idx[n2];
            const float4* cp = reinterpret_cast<const float4*>(
                cbq + (size_t)id * DDIM + dh);
            const float4* xp = reinterpret_cast<const float4*>(
                x + (size_t)(row_base + n2) * DDIM + dh);
            float* qrow = qbuf + (size_t)(row_base + n2) * DDIM + dh;
#pragma unroll
            for (int j = 0; j < 8; j++) {
                float4 cv = cp[j];
                float4 xv = xp[j];
                float4 qv;
                if (q == 0) {
                    qv.x = 0.f; qv.y = 0.f; qv.z = 0.f; qv.w = 0.f;
                } else {
                    qv = *reinterpret_cast<const float4*>(qrow + (j << 2));
                }
                float q0 = qv.x + cv.x;
                float q1 = qv.y + cv.y;
                float q2 = qv.z + cv.z;
                float q3 = qv.w + cv.w;
                float4 qo; qo.x = q0; qo.y = q1; qo.z = q2; qo.w = q3;
                *reinterpret_cast<float4*>(qrow + (j << 2)) = qo;
                int dd = dh + (j << 2);
                sts_dup(s_rT + (dd + 0) * RPAD2 + (n2 << 1), xv.x - q0);
                sts_dup(s_rT + (dd + 1) * RPAD2 + (n2 << 1), xv.y - q1);
                sts_dup(s_rT + (dd + 2) * RPAD2 + (n2 << 1), xv.z - q2);
                sts_dup(s_rT + (dd + 3) * RPAD2 + (n2 << 1), xv.w - q3);
            }
        }
        __syncthreads();
    }
    // quantized output = qbuf (accumulated in place, bit-exact ref order)
}

// ---------------- launch ----------------
extern "C" void kernel_launch(void* const* d_in, const int* in_sizes, int n_in,
                              void* d_out, int out_size) {
    const float* x = (const float*)d_in[0];
    const float* cb = (const float*)d_in[1];
    if (n_in >= 2 && in_sizes[0] == QSTAGES * KCODES * DDIM &&
        in_sizes[1] == N_ROWS * DDIM) {
        x = (const float*)d_in[1];
        cb = (const float*)d_in[0];
    }

    cudaFuncSetAttribute(rvq_kernel, cudaFuncAttributeMaxDynamicSharedMemorySize,
                         SMEM_BYTES);

    hn_kernel<<<(QSTAGES * KCODES * 32 + 255) / 256, 256>>>(cb);

    const long long enc_n = (long long)N_ROWS * QSTAGES;
    const long long qz_n = (long long)N_ROWS * DDIM;

    float* qz = nullptr;
    float* enc_f = nullptr;
    int* enc_i = nullptr;
    if ((long long)out_size == enc_n + qz_n) {
        enc_f = (float*)d_out;
        qz = (float*)d_out + enc_n;
    } else if ((long long)out_size == qz_n) {
        qz = (float*)d_out;
    } else if ((long long)out_size == enc_n) {
        enc_i = (int*)d_out;
    } else {
        enc_f = (float*)d_out;
        if ((long long)out_size >= enc_n + qz_n) qz = (float*)d_out + enc_n;
    }

    float* qbuf = qz;
    if (!qbuf) {
        cudaGetSymbolAddress((void**)&qbuf, g_qscratch);
    }

    rvq_kernel<<<N_ROWS / TM, NTHREADS, SMEM_BYTES>>>(x, cb, qbuf, enc_f, enc_i);
}

// round 11
// speedup vs baseline: 1.4033x; 1.4033x over previous
#include <cuda_runtime.h>
#include <cuda_bf16.h>
#include <cstdint>
#include <cstddef>

#define N_ROWS   262144
#define DDIM     64
#define QSTAGES  8
#define KCODES   1024
#define TMK      128
#define NCH      128            // cols per chunk
#define NCHUNKS  (KCODES / NCH)
#define NTHREADS 256
#define RS       68             // s_r row stride (fp32)
#define SB       72             // B smem row stride (bf16) -> 144B rows

#define EPSC 3e-4f
#define EPSA 1e-5f

// ---- smem layout (float units) ----
#define OFF_R    0                    // 128*68 fp32
#define OFF_B    8704                 // 2 bufs x (hi 18432B + lo 18432B)
#define OFF_HN   27136                // 1024 fp32
#define OFF_TOP  28160                // 128 x {v1, i1(as float), v2}
#define OFF_IDX  28544                // 128 ints
#define OFF_RN   28672                // 128 fp32
#define OFF_FQ   28800                // [0]=cnt [1]=mx [2..129]=queue
#define SMEM_FLOATS 28932
#define SMEM_BYTES  (SMEM_FLOATS * 4) // 115,728 B

#define BBUF_BYTES 36864              // one buf: hi+lo
#define BLO_OFF    18432              // lo offset within buf

__device__ float g_hn[QSTAGES * KCODES];
__device__ float g_mx[QSTAGES];
__device__ __nv_bfloat16 g_cbh[QSTAGES * KCODES * DDIM];
__device__ __nv_bfloat16 g_cbl[QSTAGES * KCODES * DDIM];
__device__ float g_qscratch[(size_t)N_ROWS * DDIM];

// ================= asm helpers (baseline PTX only) =================
__device__ __forceinline__ uint32_t smem_u32_of(const void* p) {
    uint32_t a;
    asm("{ .reg .u64 t; cvta.to.shared.u64 t, %1; cvt.u32.u64 %0, t; }"
        : "=r"(a) : "l"(p));
    return a;
}
__device__ __forceinline__ void ldsm_x4(uint32_t& r0, uint32_t& r1,
                                        uint32_t& r2, uint32_t& r3,
                                        uint32_t addr) {
    asm volatile("ldmatrix.sync.aligned.m8n8.x4.shared.b16 {%0,%1,%2,%3}, [%4];"
                 : "=r"(r0), "=r"(r1), "=r"(r2), "=r"(r3) : "r"(addr));
}
__device__ __forceinline__ void mma_bf16(float* d, const uint32_t* a,
                                         uint32_t b0, uint32_t b1) {
    asm volatile(
        "mma.sync.aligned.m16n8k16.row.col.f32.bf16.bf16.f32 "
        "{%0,%1,%2,%3}, {%4,%5,%6,%7}, {%8,%9}, {%0,%1,%2,%3};"
        : "+f"(d[0]), "+f"(d[1]), "+f"(d[2]), "+f"(d[3])
        : "r"(a[0]), "r"(a[1]), "r"(a[2]), "r"(a[3]), "r"(b0), "r"(b1));
}
__device__ __forceinline__ void cp16(uint32_t dst, const void* src) {
    asm volatile("cp.async.cg.shared.global [%0], [%1], 16;"
                 :: "r"(dst), "l"(src) : "memory");
}
#define CP_COMMIT() asm volatile("cp.async.commit_group;" ::: "memory")
#define CP_WAIT0()  asm volatile("cp.async.wait_group 0;" ::: "memory")
#define CP_WAIT1()  asm volatile("cp.async.wait_group 1;" ::: "memory")

__device__ __forceinline__ uint32_t pack_split(float f0, float f1,
                                               uint32_t& lo) {
    __nv_bfloat16 h0 = __float2bfloat16_rn(f0);
    __nv_bfloat16 h1 = __float2bfloat16_rn(f1);
    __nv_bfloat16 g0 = __float2bfloat16_rn(f0 - __bfloat162float(h0));
    __nv_bfloat16 g1 = __float2bfloat16_rn(f1 - __bfloat162float(h1));
    lo = (uint32_t)__bfloat16_as_ushort(g0) |
         ((uint32_t)__bfloat16_as_ushort(g1) << 16);
    return (uint32_t)__bfloat16_as_ushort(h0) |
           ((uint32_t)__bfloat16_as_ushort(h1) << 16);
}

// ================= prep kernels =================
__global__ void hn_kernel(const float* __restrict__ cb) {
    int warp = (blockIdx.x * blockDim.x + threadIdx.x) >> 5;
    int lane = threadIdx.x & 31;
    if (warp < QSTAGES * KCODES) {
        const float* row = cb + (size_t)warp * DDIM;
        float c0 = row[lane];
        float c1 = row[lane + 32];
        float acc = __fmaf_rn(c0, c0, 0.0f);
        acc = __fmaf_rn(c1, c1, acc);
#pragma unroll
        for (int off = 16; off > 0; off >>= 1)
            acc = acc + __shfl_down_sync(0xffffffffu, acc, off);
        if (lane == 0) g_hn[warp] = acc;
    }
}
__global__ void mx_kernel() {
    __shared__ float red[256];
    int q = blockIdx.x, tid = threadIdx.x;
    float m = 0.f;
    for (int i = tid; i < KCODES; i += 256) m = fmaxf(m, g_hn[q * KCODES + i]);
    red[tid] = m; __syncthreads();
    for (int s = 128; s > 0; s >>= 1) {
        if (tid < s) red[tid] = fmaxf(red[tid], red[tid + s]);
        __syncthreads();
    }
    if (tid == 0) g_mx[q] = red[0];
}
__global__ void split_kernel(const float* __restrict__ cb) {
    int gid = blockIdx.x * blockDim.x + threadIdx.x;   // code id over Q*K
    if (gid >= QSTAGES * KCODES) return;
    const float* src = cb + (size_t)gid * DDIM;
    __nv_bfloat16* bh = g_cbh + (size_t)gid * DDIM;
    __nv_bfloat16* bl = g_cbl + (size_t)gid * DDIM;
#pragma unroll
    for (int d = 0; d < DDIM; d++) {
        float f = src[d];
        __nv_bfloat16 h = __float2bfloat16_rn(f);
        bh[d] = h;
        bl[d] = __float2bfloat16_rn(f - __bfloat162float(h));
    }
}

// merge top-2 triples: smaller d wins, ties -> lower index
__device__ __forceinline__ void merge2(float& v1, int& i1, float& v2,
                                       float ov1, int oi1, float ov2) {
    if (ov1 < v1 || (ov1 == v1 && oi1 < i1)) {
        v2 = fminf(v1, ov2); v1 = ov1; i1 = oi1;
    } else {
        v2 = fminf(v2, ov1);
    }
}

// ================= main kernel =================
__global__ void __launch_bounds__(NTHREADS, 1)
rvq_mma_kernel(const float* __restrict__ x, const float* __restrict__ cb,
               float* __restrict__ qbuf, float* __restrict__ enc_f,
               int* __restrict__ enc_i) {
    extern __shared__ float smem[];
    float* s_r   = smem + OFF_R;
    float* s_hn  = smem + OFF_HN;
    float* s_top = smem + OFF_TOP;
    int*   s_idx = (int*)(smem + OFF_IDX);
    float* s_rn  = smem + OFF_RN;
    int*   s_fq  = (int*)(smem + OFF_FQ);

    const int tid = threadIdx.x;
    const int wid = tid >> 5;
    const int lane = tid & 31;
    const int g = lane >> 2;          // 0..7
    const int qd = lane & 3;          // 0..3
    const int row_base = blockIdx.x * TMK;
    const uint32_t sm_b = smem_u32_of(smem) + OFF_B * 4;
    // ldmatrix per-thread offset: row (lane&7), matrix (lane>>3) -> k += 8
    const uint32_t lm_off = ((uint32_t)(lane & 7) * SB + (uint32_t)(lane >> 3) * 8) * 2;

    // ---- init residual = x, row norms ----
    {
        int row = tid >> 1, dh = (tid & 1) << 5;
        const float4* xp = (const float4*)(x + (size_t)(row_base + row) * DDIM + dh);
        float pn = 0.f;
#pragma unroll
        for (int j = 0; j < 8; j++) {
            float4 v = xp[j];
            *(float4*)(s_r + row * RS + dh + (j << 2)) = v;
            pn = __fmaf_rn(v.x, v.x, pn); pn = __fmaf_rn(v.y, v.y, pn);
            pn = __fmaf_rn(v.z, v.z, pn); pn = __fmaf_rn(v.w, v.w, pn);
        }
        pn += __shfl_xor_sync(0xffffffffu, pn, 1);
        if ((tid & 1) == 0) s_rn[row] = pn;
    }

    for (int qs = 0; qs < QSTAGES; qs++) {
        const float* cbq = cb + (size_t)qs * (KCODES * DDIM);
        const __nv_bfloat16* cbh = g_cbh + (size_t)qs * (KCODES * DDIM);
        const __nv_bfloat16* cbl = g_cbl + (size_t)qs * (KCODES * DDIM);

#pragma unroll
        for (int i = 0; i < KCODES / NTHREADS; i++)
            s_hn[tid + i * NTHREADS] = g_hn[qs * KCODES + tid + i * NTHREADS];
        if (tid == 0) { s_fq[0] = 0; ((float*)s_fq)[1] = g_mx[qs]; }
        __syncthreads();

        // ---- A fragments (16 rows per warp), bf16 hi/lo split ----
        uint32_t ah[4][4], al[4][4];
        {
            int rlo = wid * 16 + g;
#pragma unroll
            for (int f = 0; f < 4; f++)
#pragma unroll
                for (int p = 0; p < 4; p++) {
                    int row = rlo + ((p & 1) << 3);
                    int kk = f * 16 + ((p >> 1) << 3) + (qd << 1);
                    float2 v = *(const float2*)(s_r + row * RS + kk);
                    ah[f][p] = pack_split(v.x, v.y, al[f][p]);
                }
        }

        // ---- stage chunk 0 (cp.async) ----
        {
            uint32_t dsth = sm_b;              // buf 0
#pragma unroll
            for (int t = 0; t < 4; t++) {
                int idx = t * 256 + tid;       // 1024 16B units
                int n = idx >> 3, j = idx & 7;
                uint32_t doff = (uint32_t)n * 144 + (uint32_t)j * 16;
                cp16(dsth + doff, (const char*)(cbh + (size_t)n * DDIM) + j * 16);
                cp16(dsth + BLO_OFF + doff,
                     (const char*)(cbl + (size_t)n * DDIM) + j * 16);
            }
            CP_COMMIT();
        }

        float v1l = 3.0e38f, v2l = 3.0e38f, v1h = 3.0e38f, v2h = 3.0e38f;
        int i1l = 0x7fffffff, i1h = 0x7fffffff;

        for (int c = 0; c < NCHUNKS; c++) {
            if (c < NCHUNKS - 1) {
                uint32_t dsth = sm_b + (uint32_t)((c + 1) & 1) * BBUF_BYTES;
                const __nv_bfloat16* sh = cbh + (size_t)(c + 1) * NCH * DDIM;
                const __nv_bfloat16* sl = cbl + (size_t)(c + 1) * NCH * DDIM;
#pragma unroll
                for (int t = 0; t < 4; t++) {
                    int idx = t * 256 + tid;
                    int n = idx >> 3, j = idx & 7;
                    uint32_t doff = (uint32_t)n * 144 + (uint32_t)j * 16;
                    cp16(dsth + doff, (const char*)(sh + (size_t)n * DDIM) + j * 16);
                    cp16(dsth + BLO_OFF + doff,
                         (const char*)(sl + (size_t)n * DDIM) + j * 16);
                }
                CP_COMMIT();
                CP_WAIT1();
            } else {
                CP_WAIT0();
            }
            __syncthreads();   // chunk c resident for all threads

            const uint32_t bh_base = sm_b + (uint32_t)(c & 1) * BBUF_BYTES + lm_off;
            const uint32_t bl_base = bh_base + BLO_OFF;

#pragma unroll 2
            for (int nt = 0; nt < 16; nt++) {
                uint32_t ro = (uint32_t)nt * (8 * SB * 2);
                uint32_t bh[8], bl[8];
                ldsm_x4(bh[0], bh[1], bh[2], bh[3], bh_base + ro);
                ldsm_x4(bh[4], bh[5], bh[6], bh[7], bh_base + ro + 64);
                ldsm_x4(bl[0], bl[1], bl[2], bl[3], bl_base + ro);
                ldsm_x4(bl[4], bl[5], bl[6], bl[7], bl_base + ro + 64);

                float d1[4] = {0.f, 0.f, 0.f, 0.f};
                float d2[4] = {0.f, 0.f, 0.f, 0.f};
                float d3[4] = {0.f, 0.f, 0.f, 0.f};
#pragma unroll
                for (int f = 0; f < 4; f++) {
                    mma_bf16(d1, ah[f], bh[2 * f], bh[2 * f + 1]);
                    mma_bf16(d2, ah[f], bl[2 * f], bl[2 * f + 1]);
                    mma_bf16(d3, al[f], bh[2 * f], bh[2 * f + 1]);
                }

                int cbase = c * NCH + nt * 8 + (qd << 1);
                float2 hv = *(const float2*)(s_hn + cbase);
                float s0 = (d1[0] + d2[0]) + d3[0];
                float s1 = (d1[1] + d2[1]) + d3[1];
                float s2 = (d1[2] + d2[2]) + d3[2];
                float s3 = (d1[3] + d2[3]) + d3[3];
                float dv0 = __fmaf_rn(-2.0f, s0, hv.x);
                float dv1 = __fmaf_rn(-2.0f, s1, hv.y);
                float dv2 = __fmaf_rn(-2.0f, s2, hv.x);
                float dv3 = __fmaf_rn(-2.0f, s3, hv.y);
                if (dv0 < v1l) { v2l = v1l; v1l = dv0; i1l = cbase; }
                else if (dv0 < v2l) v2l = dv0;
                if (dv1 < v1l) { v2l = v1l; v1l = dv1; i1l = cbase + 1; }
                else if (dv1 < v2l) v2l = dv1;
                if (dv2 < v1h) { v2h = v1h; v1h = dv2; i1h = cbase; }
                else if (dv2 < v2h) v2h = dv2;
                if (dv3 < v1h) { v2h = v1h; v1h = dv3; i1h = cbase + 1; }
                else if (dv3 < v2h) v2h = dv3;
            }
            __syncthreads();   // all reads of buf done before re-staging it
        }

        // ---- quad merge (lanes with same g share rows) ----
#pragma unroll
        for (int off = 1; off <= 2; off <<= 1) {
            float ov1 = __shfl_xor_sync(0xffffffffu, v1l, off);
            int oi1 = __shfl_xor_sync(0xffffffffu, i1l, off);
            float ov2 = __shfl_xor_sync(0xffffffffu, v2l, off);
            merge2(v1l, i1l, v2l, ov1, oi1, ov2);
            ov1 = __shfl_xor_sync(0xffffffffu, v1h, off);
            oi1 = __shfl_xor_sync(0xffffffffu, i1h, off);
            ov2 = __shfl_xor_sync(0xffffffffu, v2h, off);
            merge2(v1h, i1h, v2h, ov1, oi1, ov2);
        }
        if (qd == 0) {
            int rlo = wid * 16 + g;
            s_top[rlo * 3 + 0] = v1l;
            s_top[rlo * 3 + 1] = __int_as_float(i1l);
            s_top[rlo * 3 + 2] = v2l;
            s_top[(rlo + 8) * 3 + 0] = v1h;
            s_top[(rlo + 8) * 3 + 1] = __int_as_float(i1h);
            s_top[(rlo + 8) * 3 + 2] = v2h;
        }
        __syncthreads();

        // ---- eps gate ----
        if (tid < TMK) {
            float w1 = s_top[tid * 3 + 0];
            int wi = __float_as_int(s_top[tid * 3 + 1]);
            float w2 = s_top[tid * 3 + 2];
            float mx = ((float*)s_fq)[1];
            float eps = EPSC * __fsqrt_rn(s_rn[tid] * mx) + EPSA;
            if (w2 - w1 > eps) {
                s_idx[tid] = wi;
            } else {
                int p = atomicAdd(&s_fq[0], 1);
                s_fq[2 + p] = tid;
            }
        }
        __syncthreads();

        // ---- slow path: exact fp32 full-row scan (bit-exact ref order) ----
        {
            int nflag = s_fq[0];
            for (int i = wid; i < nflag; i += 8) {
                int row = s_fq[2 + i];
                float bd = 3.0e38f; int bi_ = 0x7fffffff;
                const float* rrow = s_r + row * RS;
#pragma unroll 1
                for (int j = 0; j < 32; j++) {
                    int col = lane + (j << 5);
                    const float4* cp = (const float4*)(cbq + (size_t)col * DDIM);
                    float acc = 0.f;
#pragma unroll
                    for (int u = 0; u < 16; u++) {
                        float4 cv = cp[u];
                        const float* rv = rrow + (u << 2);
                        acc = __fmaf_rn(rv[0], cv.x, acc);
                        acc = __fmaf_rn(rv[1], cv.y, acc);
                        acc = __fmaf_rn(rv[2], cv.z, acc);
                        acc = __fmaf_rn(rv[3], cv.w, acc);
                    }
                    float dv = __fmaf_rn(-2.0f, acc, s_hn[col]);
                    if (dv < bd) { bd = dv; bi_ = col; }
                }
#pragma unroll
                for (int off = 16; off > 0; off >>= 1) {
                    float ov = __shfl_xor_sync(0xffffffffu, bd, off);
                    int oi = __shfl_xor_sync(0xffffffffu, bi_, off);
                    if (ov < bd || (ov == bd && oi < bi_)) { bd = ov; bi_ = oi; }
                }
                if (lane == 0) s_idx[row] = bi_;
            }
        }
        __syncthreads();

        // ---- enc write + q/r update (bit-exact, validated) ----
        if (tid < TMK) {
            int id = s_idx[tid];
            size_t e = (size_t)(row_base + tid) * QSTAGES + qs;
            if (enc_f) enc_f[e] = (float)id;
            if (enc_i) enc_i[e] = id;
        }
        {
            int row = tid >> 1, dh = (tid & 1) << 5;
            int id = s_idx[row];
            const float4* cp = (const float4*)(cbq + (size_t)id * DDIM + dh);
            const float4* xp = (const float4*)(x + (size_t)(row_base + row) * DDIM + dh);
            float* qrow = qbuf + (size_t)(row_base + row) * DDIM + dh;
            float pn = 0.f;
#pragma unroll
            for (int j = 0; j < 8; j++) {
                float4 cv = cp[j];
                float4 xv = xp[j];
                float4 qv;
                if (qs == 0) { qv.x = qv.y = qv.z = qv.w = 0.f; }
                else qv = *(const float4*)(qrow + (j << 2));
                float q0 = qv.x + cv.x, q1 = qv.y + cv.y;
                float q2 = qv.z + cv.z, q3 = qv.w + cv.w;
                float4 qo; qo.x = q0; qo.y = q1; qo.z = q2; qo.w = q3;
                *(float4*)(qrow + (j << 2)) = qo;
                float r0 = xv.x - q0, r1 = xv.y - q1;
                float r2 = xv.z - q2, r3 = xv.w - q3;
                float4 ro; ro.x = r0; ro.y = r1; ro.z = r2; ro.w = r3;
                *(float4*)(s_r + row * RS + dh + (j << 2)) = ro;
                pn = __fmaf_rn(r0, r0, pn); pn = __fmaf_rn(r1, r1, pn);
                pn = __fmaf_rn(r2, r2, pn); pn = __fmaf_rn(r3, r3, pn);
            }
            pn += __shfl_xor_sync(0xffffffffu, pn, 1);
            if ((tid & 1) == 0) s_rn[row] = pn;
        }
        __syncthreads();
    }
}

// ---------------- launch ----------------
extern "C" void kernel_launch(void* const* d_in, const int* in_sizes, int n_in,
                              void* d_out, int out_size) {
    const float* x = (const float*)d_in[0];
    const float* cb = (const float*)d_in[1];
    if (n_in >= 2 && in_sizes[0] == QSTAGES * KCODES * DDIM &&
        in_sizes[1] == N_ROWS * DDIM) {
        x = (const float*)d_in[1];
        cb = (const float*)d_in[0];
    }

    cudaFuncSetAttribute(rvq_mma_kernel,
                         cudaFuncAttributeMaxDynamicSharedMemorySize, SMEM_BYTES);

    hn_kernel<<<(QSTAGES * KCODES * 32 + 255) / 256, 256>>>(cb);
    mx_kernel<<<QSTAGES, 256>>>();
    split_kernel<<<(QSTAGES * KCODES + 255) / 256, 256>>>(cb);

    const long long enc_n = (long long)N_ROWS * QSTAGES;
    const long long qz_n = (long long)N_ROWS * DDIM;

    float* qz = nullptr;
    float* enc_f = nullptr;
    int* enc_i = nullptr;
    if ((long long)out_size == enc_n + qz_n) {
        enc_f = (float*)d_out;
        qz = (float*)d_out + enc_n;
    } else if ((long long)out_size == qz_n) {
        qz = (float*)d_out;
    } else if ((long long)out_size == enc_n) {
        enc_i = (int*)d_out;
    } else {
        enc_f = (float*)d_out;
        if ((long long)out_size >= enc_n + qz_n) qz = (float*)d_out + enc_n;
    }

    float* qbuf = qz;
    if (!qbuf) cudaGetSymbolAddress((void**)&qbuf, g_qscratch);

    rvq_mma_kernel<<<N_ROWS / TMK, NTHREADS, SMEM_BYTES>>>(x, cb, qbuf,
                                                           enc_f, enc_i);
}

// round 13
// speedup vs baseline: 1.8122x; 1.2914x over previous
#include <cuda_runtime.h>
#include <cuda_bf16.h>
#include <cstdint>
#include <cstddef>

#define N_ROWS   262144
#define DDIM     64
#define QSTAGES  8
#define KCODES   1024
#define TMK      128
#define NCH      128            // cols per chunk
#define NCHUNKS  (KCODES / NCH)
#define NTHREADS 256
#define RS       68             // s_r row stride (fp32) — multiple of 4!
#define SB       72             // B smem row stride (bf16) -> 144B rows

#define EPSC 3e-4f
#define EPSA 1e-5f

// ---- smem layout (float units) ----
// TOP/IDX/FQ alias B buffer 1: they are only live between the end of the
// chunk loop (all buf-1 reads done) and the next stage's c=0 staging of
// buf 1 (which happens after they are fully consumed).
#define OFF_R        0                       // 128*68 = 8704 fp32
#define OFF_B        8704                    // 2 bufs x 9216 fp32
#define BBUF_FLOATS  9216                    // one buf: hi 18432B + lo 18432B
#define OFF_TOP      (OFF_B + BBUF_FLOATS)   // 17920 (aliases buf 1)
#define OFF_IDX      (OFF_TOP + 384)         // 18304
#define OFF_FQ       (OFF_IDX + 128)         // 18432 ([0]=cnt [1]=mx [2..]=queue)
#define OFF_HN       (OFF_B + 2 * BBUF_FLOATS) // 27136
#define SMEM_FLOATS  (OFF_HN + KCODES)       // 28160
#define SMEM_BYTES   (SMEM_FLOATS * 4)       // 112,640 B (x2 CTAs = 225,280)

#define BBUF_BYTES 36864
#define BLO_OFF    18432

__device__ float g_hn[QSTAGES * KCODES];
__device__ float g_mx[QSTAGES];
__device__ __nv_bfloat16 g_cbh[QSTAGES * KCODES * DDIM];
__device__ __nv_bfloat16 g_cbl[QSTAGES * KCODES * DDIM];
__device__ float g_qscratch[(size_t)N_ROWS * DDIM];

// ================= asm helpers (baseline PTX only) =================
__device__ __forceinline__ uint32_t smem_u32_of(const void* p) {
    uint32_t a;
    asm("{ .reg .u64 t; cvta.to.shared.u64 t, %1; cvt.u32.u64 %0, t; }"
        : "=r"(a) : "l"(p));
    return a;
}
__device__ __forceinline__ void ldsm_x4(uint32_t& r0, uint32_t& r1,
                                        uint32_t& r2, uint32_t& r3,
                                        uint32_t addr) {
    asm volatile("ldmatrix.sync.aligned.m8n8.x4.shared.b16 {%0,%1,%2,%3}, [%4];"
                 : "=r"(r0), "=r"(r1), "=r"(r2), "=r"(r3) : "r"(addr));
}
__device__ __forceinline__ void mma_bf16(float* d, const uint32_t* a,
                                         uint32_t b0, uint32_t b1) {
    asm volatile(
        "mma.sync.aligned.m16n8k16.row.col.f32.bf16.bf16.f32 "
        "{%0,%1,%2,%3}, {%4,%5,%6,%7}, {%8,%9}, {%0,%1,%2,%3};"
        : "+f"(d[0]), "+f"(d[1]), "+f"(d[2]), "+f"(d[3])
        : "r"(a[0]), "r"(a[1]), "r"(a[2]), "r"(a[3]), "r"(b0), "r"(b1));
}
__device__ __forceinline__ void cp16(uint32_t dst, const void* src) {
    asm volatile("cp.async.cg.shared.global [%0], [%1], 16;"
                 :: "r"(dst), "l"(src) : "memory");
}
#define CP_COMMIT() asm volatile("cp.async.commit_group;" ::: "memory")
#define CP_WAIT0()  asm volatile("cp.async.wait_group 0;" ::: "memory")
#define CP_WAIT1()  asm volatile("cp.async.wait_group 1;" ::: "memory")

__device__ __forceinline__ uint32_t pack_split(float f0, float f1,
                                               uint32_t& lo) {
    __nv_bfloat16 h0 = __float2bfloat16_rn(f0);
    __nv_bfloat16 h1 = __float2bfloat16_rn(f1);
    __nv_bfloat16 g0 = __float2bfloat16_rn(f0 - __bfloat162float(h0));
    __nv_bfloat16 g1 = __float2bfloat16_rn(f1 - __bfloat162float(h1));
    lo = (uint32_t)__bfloat16_as_ushort(g0) |
         ((uint32_t)__bfloat16_as_ushort(g1) << 16);
    return (uint32_t)__bfloat16_as_ushort(h0) |
           ((uint32_t)__bfloat16_as_ushort(h1) << 16);
}

// ================= prep kernels =================
__global__ void hn_kernel(const float* __restrict__ cb) {
    int warp = (blockIdx.x * blockDim.x + threadIdx.x) >> 5;
    int lane = threadIdx.x & 31;
    if (warp < QSTAGES * KCODES) {
        const float* row = cb + (size_t)warp * DDIM;
        float c0 = row[lane];
        float c1 = row[lane + 32];
        float acc = __fmaf_rn(c0, c0, 0.0f);
        acc = __fmaf_rn(c1, c1, acc);
#pragma unroll
        for (int off = 16; off > 0; off >>= 1)
            acc = acc + __shfl_down_sync(0xffffffffu, acc, off);
        if (lane == 0) g_hn[warp] = acc;
    }
}
__global__ void mx_kernel() {
    __shared__ float red[256];
    int q = blockIdx.x, tid = threadIdx.x;
    float m = 0.f;
    for (int i = tid; i < KCODES; i += 256) m = fmaxf(m, g_hn[q * KCODES + i]);
    red[tid] = m; __syncthreads();
    for (int s = 128; s > 0; s >>= 1) {
        if (tid < s) red[tid] = fmaxf(red[tid], red[tid + s]);
        __syncthreads();
    }
    if (tid == 0) g_mx[q] = red[0];
}
__global__ void split_kernel(const float* __restrict__ cb) {
    int gid = blockIdx.x * blockDim.x + threadIdx.x;   // code id over Q*K
    if (gid >= QSTAGES * KCODES) return;
    const float* src = cb + (size_t)gid * DDIM;
    __nv_bfloat16* bh = g_cbh + (size_t)gid * DDIM;
    __nv_bfloat16* bl = g_cbl + (size_t)gid * DDIM;
#pragma unroll
    for (int d = 0; d < DDIM; d++) {
        float f = src[d];
        __nv_bfloat16 h = __float2bfloat16_rn(f);
        bh[d] = h;
        bl[d] = __float2bfloat16_rn(f - __bfloat162float(h));
    }
}

// merge top-2 triples: smaller d wins, ties -> lower index
__device__ __forceinline__ void merge2(float& v1, int& i1, float& v2,
                                       float ov1, int oi1, float ov2) {
    if (ov1 < v1 || (ov1 == v1 && oi1 < i1)) {
        v2 = fminf(v1, ov2); v1 = ov1; i1 = oi1;
    } else {
        v2 = fminf(v2, ov1);
    }
}

// ================= main kernel =================
__global__ void __launch_bounds__(NTHREADS, 2)
rvq_mma_kernel(const float* __restrict__ x, const float* __restrict__ cb,
               float* __restrict__ qbuf, float* __restrict__ enc_f,
               int* __restrict__ enc_i) {
    extern __shared__ float smem[];
    float* s_r   = smem + OFF_R;
    float* s_hn  = smem + OFF_HN;
    float* s_top = smem + OFF_TOP;
    int*   s_idx = (int*)(smem + OFF_IDX);
    int*   s_fq  = (int*)(smem + OFF_FQ);

    const int tid = threadIdx.x;
    const int wid = tid >> 5;
    const int lane = tid & 31;
    const int g = lane >> 2;          // 0..7
    const int qd = lane & 3;          // 0..3
    const int row_base = blockIdx.x * TMK;
    const uint32_t sm_b = smem_u32_of(smem) + OFF_B * 4;
    // ldmatrix per-thread offset: row (lane&7), matrix (lane>>3) -> k += 8
    const uint32_t lm_off = ((uint32_t)(lane & 7) * SB + (uint32_t)(lane >> 3) * 8) * 2;

    // ---- init residual = x ----
    {
        int row = tid >> 1, dh = (tid & 1) << 5;
        const float4* xp = (const float4*)(x + (size_t)(row_base + row) * DDIM + dh);
#pragma unroll
        for (int j = 0; j < 8; j++)
            *(float4*)(s_r + row * RS + dh + (j << 2)) = xp[j];
    }

    for (int qs = 0; qs < QSTAGES; qs++) {
        const float* cbq = cb + (size_t)qs * (KCODES * DDIM);
        const __nv_bfloat16* cbh = g_cbh + (size_t)qs * (KCODES * DDIM);
        const __nv_bfloat16* cbl = g_cbl + (size_t)qs * (KCODES * DDIM);

#pragma unroll
        for (int i = 0; i < KCODES / NTHREADS; i++)
            s_hn[tid + i * NTHREADS] = g_hn[qs * KCODES + tid + i * NTHREADS];
        __syncthreads();

        // ---- A fragments (16 rows per warp), bf16 hi/lo split ----
        uint32_t ah[4][4], al[4][4];
        {
            int rlo = wid * 16 + g;
#pragma unroll
            for (int f = 0; f < 4; f++)
#pragma unroll
                for (int p = 0; p < 4; p++) {
                    int row = rlo + ((p & 1) << 3);
                    int kk = f * 16 + ((p >> 1) << 3) + (qd << 1);
                    float2 v = *(const float2*)(s_r + row * RS + kk);
                    ah[f][p] = pack_split(v.x, v.y, al[f][p]);
                }
        }

        // ---- stage chunk 0 (cp.async) into buf 0 ----
        {
            uint32_t dsth = sm_b;
#pragma unroll
            for (int t = 0; t < 4; t++) {
                int idx = t * 256 + tid;       // 1024 16B units
                int n = idx >> 3, j = idx & 7;
                uint32_t doff = (uint32_t)n * 144 + (uint32_t)j * 16;
                cp16(dsth + doff, (const char*)(cbh + (size_t)n * DDIM) + j * 16);
                cp16(dsth + BLO_OFF + doff,
                     (const char*)(cbl + (size_t)n * DDIM) + j * 16);
            }
            CP_COMMIT();
        }

        float v1l = 3.0e38f, v2l = 3.0e38f, v1h = 3.0e38f, v2h = 3.0e38f;
        int i1l = 0x7fffffff, i1h = 0x7fffffff;

        for (int c = 0; c < NCHUNKS; c++) {
            if (c < NCHUNKS - 1) {
                uint32_t dsth = sm_b + (uint32_t)((c + 1) & 1) * BBUF_BYTES;
                const __nv_bfloat16* sh = cbh + (size_t)(c + 1) * NCH * DDIM;
                const __nv_bfloat16* sl = cbl + (size_t)(c + 1) * NCH * DDIM;
#pragma unroll
                for (int t = 0; t < 4; t++) {
                    int idx = t * 256 + tid;
                    int n = idx >> 3, j = idx & 7;
                    uint32_t doff = (uint32_t)n * 144 + (uint32_t)j * 16;
                    cp16(dsth + doff, (const char*)(sh + (size_t)n * DDIM) + j * 16);
                    cp16(dsth + BLO_OFF + doff,
                         (const char*)(sl + (size_t)n * DDIM) + j * 16);
                }
                CP_COMMIT();
                CP_WAIT1();
            } else {
                CP_WAIT0();
            }
            __syncthreads();   // chunk c resident for all threads

            const uint32_t bh_base = sm_b + (uint32_t)(c & 1) * BBUF_BYTES + lm_off;
            const uint32_t bl_base = bh_base + BLO_OFF;

#pragma unroll 2
            for (int nt = 0; nt < 16; nt++) {
                uint32_t ro = (uint32_t)nt * (8 * SB * 2);
                float d1[4] = {0.f, 0.f, 0.f, 0.f};
                float d2[4] = {0.f, 0.f, 0.f, 0.f};
                float d3[4] = {0.f, 0.f, 0.f, 0.f};
                {
                    uint32_t bh[8];
                    ldsm_x4(bh[0], bh[1], bh[2], bh[3], bh_base + ro);
                    ldsm_x4(bh[4], bh[5], bh[6], bh[7], bh_base + ro + 64);
#pragma unroll
                    for (int f = 0; f < 4; f++) {
                        mma_bf16(d1, ah[f], bh[2 * f], bh[2 * f + 1]);
                        mma_bf16(d3, al[f], bh[2 * f], bh[2 * f + 1]);
                    }
                }
                {
                    uint32_t bl[8];
                    ldsm_x4(bl[0], bl[1], bl[2], bl[3], bl_base + ro);
                    ldsm_x4(bl[4], bl[5], bl[6], bl[7], bl_base + ro + 64);
#pragma unroll
                    for (int f = 0; f < 4; f++)
                        mma_bf16(d2, ah[f], bl[2 * f], bl[2 * f + 1]);
                }

                int cbase = c * NCH + nt * 8 + (qd << 1);
                float2 hv = *(const float2*)(s_hn + cbase);
                float s0 = (d1[0] + d2[0]) + d3[0];
                float s1 = (d1[1] + d2[1]) + d3[1];
                float s2 = (d1[2] + d2[2]) + d3[2];
                float s3 = (d1[3] + d2[3]) + d3[3];
                float dv0 = __fmaf_rn(-2.0f, s0, hv.x);
                float dv1 = __fmaf_rn(-2.0f, s1, hv.y);
                float dv2 = __fmaf_rn(-2.0f, s2, hv.x);
                float dv3 = __fmaf_rn(-2.0f, s3, hv.y);
                if (dv0 < v1l) { v2l = v1l; v1l = dv0; i1l = cbase; }
                else if (dv0 < v2l) v2l = dv0;
                if (dv1 < v1l) { v2l = v1l; v1l = dv1; i1l = cbase + 1; }
                else if (dv1 < v2l) v2l = dv1;
                if (dv2 < v1h) { v2h = v1h; v1h = dv2; i1h = cbase; }
                else if (dv2 < v2h) v2h = dv2;
                if (dv3 < v1h) { v2h = v1h; v1h = dv3; i1h = cbase + 1; }
                else if (dv3 < v2h) v2h = dv3;
            }
            __syncthreads();   // all reads of buf done before re-staging it
        }
        // NOTE: from here to the end of the stage, buf 1 region is reused
        // for s_top / s_idx / s_fq (no B reads remain; next B write is
        // next stage's c=0 staging, which is after the update sync).

        // ---- quad merge (lanes with same g share rows) ----
#pragma unroll
        for (int off = 1; off <= 2; off <<= 1) {
            float ov1 = __shfl_xor_sync(0xffffffffu, v1l, off);
            int oi1 = __shfl_xor_sync(0xffffffffu, i1l, off);
            float ov2 = __shfl_xor_sync(0xffffffffu, v2l, off);
            merge2(v1l, i1l, v2l, ov1, oi1, ov2);
            ov1 = __shfl_xor_sync(0xffffffffu, v1h, off);
            oi1 = __shfl_xor_sync(0xffffffffu, i1h, off);
            ov2 = __shfl_xor_sync(0xffffffffu, v2h, off);
            merge2(v1h, i1h, v2h, ov1, oi1, ov2);
        }
        if (qd == 0) {
            int rlo = wid * 16 + g;
            s_top[rlo * 3 + 0] = v1l;
            s_top[rlo * 3 + 1] = __int_as_float(i1l);
            s_top[rlo * 3 + 2] = v2l;
            s_top[(rlo + 8) * 3 + 0] = v1h;
            s_top[(rlo + 8) * 3 + 1] = __int_as_float(i1h);
            s_top[(rlo + 8) * 3 + 2] = v2h;
        }
        if (tid == 0) { s_fq[0] = 0; ((float*)s_fq)[1] = g_mx[qs]; }
        __syncthreads();

        // ---- eps gate (row norm recomputed; order-free, only feeds eps) ----
        if (tid < TMK) {
            float w1 = s_top[tid * 3 + 0];
            int wi = __float_as_int(s_top[tid * 3 + 1]);
            float w2 = s_top[tid * 3 + 2];
            const float* rr = s_r + tid * RS;
            float pn = 0.f;
#pragma unroll
            for (int u = 0; u < 16; u++) {
                float4 v = *(const float4*)(rr + (u << 2));
                pn = __fmaf_rn(v.x, v.x, pn); pn = __fmaf_rn(v.y, v.y, pn);
                pn = __fmaf_rn(v.z, v.z, pn); pn = __fmaf_rn(v.w, v.w, pn);
            }
            float mx = ((float*)s_fq)[1];
            float eps = EPSC * __fsqrt_rn(pn * mx) + EPSA;
            if (w2 - w1 > eps) {
                s_idx[tid] = wi;
            } else {
                int p = atomicAdd(&s_fq[0], 1);
                s_fq[2 + p] = tid;
            }
        }
        __syncthreads();

        // ---- slow path: exact fp32 full-row scan (bit-exact ref order) ----
        {
            int nflag = s_fq[0];
            for (int i = wid; i < nflag; i += 8) {
                int row = s_fq[2 + i];
                float bd = 3.0e38f; int bi_ = 0x7fffffff;
                const float* rrow = s_r + row * RS;
#pragma unroll 1
                for (int j = 0; j < 32; j++) {
                    int col = lane + (j << 5);
                    const float4* cp = (const float4*)(cbq + (size_t)col * DDIM);
                    float acc = 0.f;
#pragma unroll
                    for (int u = 0; u < 16; u++) {
                        float4 cv = cp[u];
                        const float* rv = rrow + (u << 2);
                        acc = __fmaf_rn(rv[0], cv.x, acc);
                        acc = __fmaf_rn(rv[1], cv.y, acc);
                        acc = __fmaf_rn(rv[2], cv.z, acc);
                        acc = __fmaf_rn(rv[3], cv.w, acc);
                    }
                    float dv = __fmaf_rn(-2.0f, acc, s_hn[col]);
                    if (dv < bd) { bd = dv; bi_ = col; }
                }
#pragma unroll
                for (int off = 16; off > 0; off >>= 1) {
                    float ov = __shfl_xor_sync(0xffffffffu, bd, off);
                    int oi = __shfl_xor_sync(0xffffffffu, bi_, off);
                    if (ov < bd || (ov == bd && oi < bi_)) { bd = ov; bi_ = oi; }
                }
                if (lane == 0) s_idx[row] = bi_;
            }
        }
        __syncthreads();

        // ---- enc write + q/r update (bit-exact, validated) ----
        if (tid < TMK) {
            int id = s_idx[tid];
            size_t e = (size_t)(row_base + tid) * QSTAGES + qs;
            if (enc_f) enc_f[e] = (float)id;
            if (enc_i) enc_i[e] = id;
        }
        {
            int row = tid >> 1, dh = (tid & 1) << 5;
            int id = s_idx[row];
            const float4* cp = (const float4*)(cbq + (size_t)id * DDIM + dh);
            const float4* xp = (const float4*)(x + (size_t)(row_base + row) * DDIM + dh);
            float* qrow = qbuf + (size_t)(row_base + row) * DDIM + dh;
#pragma unroll
            for (int j = 0; j < 8; j++) {
                float4 cv = cp[j];
                float4 xv = xp[j];
                float4 qv;
                if (qs == 0) { qv.x = qv.y = qv.z = qv.w = 0.f; }
                else qv = *(const float4*)(qrow + (j << 2));
                float q0 = qv.x + cv.x, q1 = qv.y + cv.y;
                float q2 = qv.z + cv.z, q3 = qv.w + cv.w;
                float4 qo; qo.x = q0; qo.y = q1; qo.z = q2; qo.w = q3;
                *(float4*)(qrow + (j << 2)) = qo;
                float4 ro;
                ro.x = xv.x - q0; ro.y = xv.y - q1;
                ro.z = xv.z - q2; ro.w = xv.w - q3;
                *(float4*)(s_r + row * RS + dh + (j << 2)) = ro;
            }
        }
        __syncthreads();
    }
}

// ---------------- launch ----------------
extern "C" void kernel_launch(void* const* d_in, const int* in_sizes, int n_in,
                              void* d_out, int out_size) {
    const float* x = (const float*)d_in[0];
    const float* cb = (const float*)d_in[1];
    if (n_in >= 2 && in_sizes[0] == QSTAGES * KCODES * DDIM &&
        in_sizes[1] == N_ROWS * DDIM) {
        x = (const float*)d_in[1];
        cb = (const float*)d_in[0];
    }

    cudaFuncSetAttribute(rvq_mma_kernel,
                         cudaFuncAttributeMaxDynamicSharedMemorySize, SMEM_BYTES);

    hn_kernel<<<(QSTAGES * KCODES * 32 + 255) / 256, 256>>>(cb);
    mx_kernel<<<QSTAGES, 256>>>();
    split_kernel<<<(QSTAGES * KCODES + 255) / 256, 256>>>(cb);

    const long long enc_n = (long long)N_ROWS * QSTAGES;
    const long long qz_n = (long long)N_ROWS * DDIM;

    float* qz = nullptr;
    float* enc_f = nullptr;
    int* enc_i = nullptr;
    if ((long long)out_size == enc_n + qz_n) {
        enc_f = (float*)d_out;
        qz = (float*)d_out + enc_n;
    } else if ((long long)out_size == qz_n) {
        qz = (float*)d_out;
    } else if ((long long)out_size == enc_n) {
        enc_i = (int*)d_out;
    } else {
        enc_f = (float*)d_out;
        if ((long long)out_size >= enc_n + qz_n) qz = (float*)d_out + enc_n;
    }

    float* qbuf = qz;
    if (!qbuf) cudaGetSymbolAddress((void**)&qbuf, g_qscratch);

    rvq_mma_kernel<<<N_ROWS / TMK, NTHREADS, SMEM_BYTES>>>(x, cb, qbuf,
                                                           enc_f, enc_i);
}

// round 14
// speedup vs baseline: 2.0107x; 1.1095x over previous
#include <cuda_runtime.h>
#include <cuda_bf16.h>
#include <cstdint>
#include <cstddef>

#define N_ROWS   262144
#define DDIM     64
#define QSTAGES  8
#define KCODES   1024
#define TMK      128
#define NCH      128            // cols per chunk
#define NCHUNKS  (KCODES / NCH)
#define NTHREADS 256
#define RS       68             // s_r row stride (fp32) — multiple of 4!
#define SB       72             // B smem row stride (bf16) -> 144B rows

#define EPSC 3e-4f
#define EPSA 1e-5f

// ---- smem layout (float units) ----
// TOP/IDX/FQ alias B buffer 1 (lifetimes disjoint: written after the chunk
// loop's last sync, consumed before next stage's c=0 staging of buf 1).
#define OFF_R        0                        // 128*68 = 8704 fp32
#define OFF_B        8704                     // 2 bufs x 9216 fp32
#define BBUF_FLOATS  9216                     // one buf: hi 18432B + lo 18432B
#define OFF_TOP      (OFF_B + BBUF_FLOATS)    // 17920 (aliases buf 1): 768
#define OFF_IDX      (OFF_TOP + 768)          // 18688: 128 ints
#define OFF_FQ       (OFF_IDX + 128)          // 18816: cnt, mx, queue[128]
#define OFF_HN       (OFF_B + 2 * BBUF_FLOATS) // 27136
#define SMEM_FLOATS  (OFF_HN + KCODES)        // 28160
#define SMEM_BYTES   (SMEM_FLOATS * 4)        // 112,640 B (x2 CTAs = 225,280)

#define BBUF_BYTES 36864
#define BLO_OFF    18432

__device__ float g_hn[QSTAGES * KCODES];
__device__ float g_mx[QSTAGES];
__device__ __nv_bfloat16 g_cbh[QSTAGES * KCODES * DDIM];
__device__ __nv_bfloat16 g_cbl[QSTAGES * KCODES * DDIM];
__device__ float g_qscratch[(size_t)N_ROWS * DDIM];

// ================= asm helpers (baseline PTX only) =================
__device__ __forceinline__ uint32_t smem_u32_of(const void* p) {
    uint32_t a;
    asm("{ .reg .u64 t; cvta.to.shared.u64 t, %1; cvt.u32.u64 %0, t; }"
        : "=r"(a) : "l"(p));
    return a;
}
__device__ __forceinline__ void ldsm_x4(uint32_t& r0, uint32_t& r1,
                                        uint32_t& r2, uint32_t& r3,
                                        uint32_t addr) {
    asm volatile("ldmatrix.sync.aligned.m8n8.x4.shared.b16 {%0,%1,%2,%3}, [%4];"
                 : "=r"(r0), "=r"(r1), "=r"(r2), "=r"(r3) : "r"(addr));
}
__device__ __forceinline__ void mma_bf16(float* d, const uint32_t* a,
                                         uint32_t b0, uint32_t b1) {
    asm volatile(
        "mma.sync.aligned.m16n8k16.row.col.f32.bf16.bf16.f32 "
        "{%0,%1,%2,%3}, {%4,%5,%6,%7}, {%8,%9}, {%0,%1,%2,%3};"
        : "+f"(d[0]), "+f"(d[1]), "+f"(d[2]), "+f"(d[3])
        : "r"(a[0]), "r"(a[1]), "r"(a[2]), "r"(a[3]), "r"(b0), "r"(b1));
}
__device__ __forceinline__ void cp16(uint32_t dst, const void* src) {
    asm volatile("cp.async.cg.shared.global [%0], [%1], 16;"
                 :: "r"(dst), "l"(src) : "memory");
}
#define CP_COMMIT() asm volatile("cp.async.commit_group;" ::: "memory")
#define CP_WAIT0()  asm volatile("cp.async.wait_group 0;" ::: "memory")
#define CP_WAIT1()  asm volatile("cp.async.wait_group 1;" ::: "memory")

__device__ __forceinline__ uint32_t pack_split(float f0, float f1,
                                               uint32_t& lo) {
    __nv_bfloat16 h0 = __float2bfloat16_rn(f0);
    __nv_bfloat16 h1 = __float2bfloat16_rn(f1);
    __nv_bfloat16 g0 = __float2bfloat16_rn(f0 - __bfloat162float(h0));
    __nv_bfloat16 g1 = __float2bfloat16_rn(f1 - __bfloat162float(h1));
    lo = (uint32_t)__bfloat16_as_ushort(g0) |
         ((uint32_t)__bfloat16_as_ushort(g1) << 16);
    return (uint32_t)__bfloat16_as_ushort(h0) |
           ((uint32_t)__bfloat16_as_ushort(h1) << 16);
}

// ================= prep kernels =================
__global__ void hn_kernel(const float* __restrict__ cb) {
    int warp = (blockIdx.x * blockDim.x + threadIdx.x) >> 5;
    int lane = threadIdx.x & 31;
    if (warp < QSTAGES * KCODES) {
        const float* row = cb + (size_t)warp * DDIM;
        float c0 = row[lane];
        float c1 = row[lane + 32];
        float acc = __fmaf_rn(c0, c0, 0.0f);
        acc = __fmaf_rn(c1, c1, acc);
#pragma unroll
        for (int off = 16; off > 0; off >>= 1)
            acc = acc + __shfl_down_sync(0xffffffffu, acc, off);
        if (lane == 0) g_hn[warp] = acc;
    }
}
__global__ void mx_kernel() {
    __shared__ float red[256];
    int q = blockIdx.x, tid = threadIdx.x;
    float m = 0.f;
    for (int i = tid; i < KCODES; i += 256) m = fmaxf(m, g_hn[q * KCODES + i]);
    red[tid] = m; __syncthreads();
    for (int s = 128; s > 0; s >>= 1) {
        if (tid < s) red[tid] = fmaxf(red[tid], red[tid + s]);
        __syncthreads();
    }
    if (tid == 0) g_mx[q] = red[0];
}
__global__ void split_kernel(const float* __restrict__ cb) {
    int gid = blockIdx.x * blockDim.x + threadIdx.x;
    if (gid >= QSTAGES * KCODES) return;
    const float* src = cb + (size_t)gid * DDIM;
    __nv_bfloat16* bh = g_cbh + (size_t)gid * DDIM;
    __nv_bfloat16* bl = g_cbl + (size_t)gid * DDIM;
#pragma unroll
    for (int d = 0; d < DDIM; d++) {
        float f = src[d];
        __nv_bfloat16 h = __float2bfloat16_rn(f);
        bh[d] = h;
        bl[d] = __float2bfloat16_rn(f - __bfloat162float(h));
    }
}

// merge top-2 triples: smaller d wins, ties -> lower index
__device__ __forceinline__ void merge2(float& v1, int& i1, float& v2,
                                       float ov1, int oi1, float ov2) {
    if (ov1 < v1 || (ov1 == v1 && oi1 < i1)) {
        v2 = fminf(v1, ov2); v1 = ov1; i1 = oi1;
    } else {
        v2 = fminf(v2, ov1);
    }
}

// pairwise top-2 update: candidates (dv0@c0, dv1@c0+1)
__device__ __forceinline__ void upd_pair(float& v1, int& i1, float& v2,
                                         float dv0, float dv1, int c0) {
    float m = fminf(dv0, dv1);
    float loser = fmaxf(dv0, dv1);
    int im = (dv1 < dv0) ? (c0 + 1) : c0;   // tie -> lower index
    if (m < v1) { v2 = fminf(v1, loser); v1 = m; i1 = im; }
    else        { v2 = fminf(v2, m); }
}

// ================= main kernel =================
__global__ void __launch_bounds__(NTHREADS, 2)
rvq_mma_kernel(const float* __restrict__ x, const float* __restrict__ cb,
               float* __restrict__ qbuf, float* __restrict__ enc_f,
               int* __restrict__ enc_i) {
    extern __shared__ float smem[];
    float* s_r   = smem + OFF_R;
    float* s_hn  = smem + OFF_HN;
    float* s_top = smem + OFF_TOP;
    int*   s_idx = (int*)(smem + OFF_IDX);
    int*   s_fq  = (int*)(smem + OFF_FQ);

    const int tid = threadIdx.x;
    const int wid = tid >> 5;
    const int lane = tid & 31;
    const int g = lane >> 2;          // 0..7
    const int qd = lane & 3;          // 0..3
    const int rhalf = wid & 3;        // row quarter (32 rows)
    const int chalf = wid >> 2;       // col half (64 cols)
    const int row_base = blockIdx.x * TMK;
    const uint32_t sm_b = smem_u32_of(smem) + OFF_B * 4;
    const uint32_t lm_off = ((uint32_t)(lane & 7) * SB + (uint32_t)(lane >> 3) * 8) * 2
                          + (uint32_t)chalf * 64 * SB * 2;

    // ---- init residual = x ----
    {
        int row = tid >> 1, dh = (tid & 1) << 5;
        const float4* xp = (const float4*)(x + (size_t)(row_base + row) * DDIM + dh);
#pragma unroll
        for (int j = 0; j < 8; j++)
            *(float4*)(s_r + row * RS + dh + (j << 2)) = xp[j];
    }

    for (int qs = 0; qs < QSTAGES; qs++) {
        const float* cbq = cb + (size_t)qs * (KCODES * DDIM);
        const __nv_bfloat16* cbh = g_cbh + (size_t)qs * (KCODES * DDIM);
        const __nv_bfloat16* cbl = g_cbl + (size_t)qs * (KCODES * DDIM);

#pragma unroll
        for (int i = 0; i < KCODES / NTHREADS; i++)
            s_hn[tid + i * NTHREADS] = g_hn[qs * KCODES + tid + i * NTHREADS];
        __syncthreads();

        // ---- A fragments (32 rows per warp, 2 rowfrags), bf16 hi/lo ----
        uint32_t ah[2][4][4], al[2][4][4];
        {
            int rlo = rhalf * 32 + g;
#pragma unroll
            for (int rf = 0; rf < 2; rf++)
#pragma unroll
                for (int f = 0; f < 4; f++)
#pragma unroll
                    for (int p = 0; p < 4; p++) {
                        int row = rlo + rf * 16 + ((p & 1) << 3);
                        int kk = f * 16 + ((p >> 1) << 3) + (qd << 1);
                        float2 v = *(const float2*)(s_r + row * RS + kk);
                        ah[rf][f][p] = pack_split(v.x, v.y, al[rf][f][p]);
                    }
        }

        // ---- stage chunk 0 (cp.async) into buf 0 ----
        {
            uint32_t dsth = sm_b;
#pragma unroll
            for (int t = 0; t < 4; t++) {
                int idx = t * 256 + tid;
                int n = idx >> 3, j = idx & 7;
                uint32_t doff = (uint32_t)n * 144 + (uint32_t)j * 16;
                cp16(dsth + doff, (const char*)(cbh + (size_t)n * DDIM) + j * 16);
                cp16(dsth + BLO_OFF + doff,
                     (const char*)(cbl + (size_t)n * DDIM) + j * 16);
            }
            CP_COMMIT();
        }

        // top-2 state: 4 row slots (rf*2 + (0: row g, 1: row g+8))
        float v1[4], v2[4];
        int i1[4];
#pragma unroll
        for (int s = 0; s < 4; s++) {
            v1[s] = 3.0e38f; v2[s] = 3.0e38f; i1[s] = 0x7fffffff;
        }

        for (int c = 0; c < NCHUNKS; c++) {
            if (c < NCHUNKS - 1) {
                uint32_t dsth = sm_b + (uint32_t)((c + 1) & 1) * BBUF_BYTES;
                const __nv_bfloat16* sh = cbh + (size_t)(c + 1) * NCH * DDIM;
                const __nv_bfloat16* sl = cbl + (size_t)(c + 1) * NCH * DDIM;
#pragma unroll
                for (int t = 0; t < 4; t++) {
                    int idx = t * 256 + tid;
                    int n = idx >> 3, j = idx & 7;
                    uint32_t doff = (uint32_t)n * 144 + (uint32_t)j * 16;
                    cp16(dsth + doff, (const char*)(sh + (size_t)n * DDIM) + j * 16);
                    cp16(dsth + BLO_OFF + doff,
                         (const char*)(sl + (size_t)n * DDIM) + j * 16);
                }
                CP_COMMIT();
                CP_WAIT1();
            } else {
                CP_WAIT0();
            }
            __syncthreads();

            const uint32_t bh_base = sm_b + (uint32_t)(c & 1) * BBUF_BYTES + lm_off;
            const uint32_t bl_base = bh_base + BLO_OFF;

#pragma unroll 1
            for (int nt = 0; nt < 8; nt++) {
                uint32_t ro = (uint32_t)nt * (8 * SB * 2);
                uint32_t bh[8], bl[8];
                ldsm_x4(bh[0], bh[1], bh[2], bh[3], bh_base + ro);
                ldsm_x4(bh[4], bh[5], bh[6], bh[7], bh_base + ro + 64);
                ldsm_x4(bl[0], bl[1], bl[2], bl[3], bl_base + ro);
                ldsm_x4(bl[4], bl[5], bl[6], bl[7], bl_base + ro + 64);

                int cbase = c * NCH + chalf * 64 + nt * 8 + (qd << 1);
                float2 hv = *(const float2*)(s_hn + cbase);

#pragma unroll
                for (int rf = 0; rf < 2; rf++) {
                    float d1[4] = {0.f, 0.f, 0.f, 0.f};
                    float d2[4] = {0.f, 0.f, 0.f, 0.f};
                    float d3[4] = {0.f, 0.f, 0.f, 0.f};
#pragma unroll
                    for (int f = 0; f < 4; f++) {
                        mma_bf16(d1, ah[rf][f], bh[2 * f], bh[2 * f + 1]);
                        mma_bf16(d3, al[rf][f], bh[2 * f], bh[2 * f + 1]);
                        mma_bf16(d2, ah[rf][f], bl[2 * f], bl[2 * f + 1]);
                    }
                    float s0 = (d1[0] + d2[0]) + d3[0];
                    float s1 = (d1[1] + d2[1]) + d3[1];
                    float s2 = (d1[2] + d2[2]) + d3[2];
                    float s3 = (d1[3] + d2[3]) + d3[3];
                    float dv0 = __fmaf_rn(-2.0f, s0, hv.x);
                    float dv1 = __fmaf_rn(-2.0f, s1, hv.y);
                    float dv2 = __fmaf_rn(-2.0f, s2, hv.x);
                    float dv3 = __fmaf_rn(-2.0f, s3, hv.y);
                    int s0i = rf * 2;
                    upd_pair(v1[s0i], i1[s0i], v2[s0i], dv0, dv1, cbase);
                    upd_pair(v1[s0i + 1], i1[s0i + 1], v2[s0i + 1], dv2, dv3, cbase);
                }
            }
            __syncthreads();
        }
        // From here, buf 1 region reused for s_top / s_idx / s_fq.

        // ---- quad merge (lanes with same g share rows) ----
#pragma unroll
        for (int s = 0; s < 4; s++) {
#pragma unroll
            for (int off = 1; off <= 2; off <<= 1) {
                float ov1 = __shfl_xor_sync(0xffffffffu, v1[s], off);
                int oi1 = __shfl_xor_sync(0xffffffffu, i1[s], off);
                float ov2 = __shfl_xor_sync(0xffffffffu, v2[s], off);
                merge2(v1[s], i1[s], v2[s], ov1, oi1, ov2);
            }
        }
        if (qd == 0) {
            int rlo = rhalf * 32 + g;
#pragma unroll
            for (int s = 0; s < 4; s++) {
                int row = rlo + ((s & 1) << 3) + ((s >> 1) << 4);
                s_top[row * 6 + chalf * 3 + 0] = v1[s];
                s_top[row * 6 + chalf * 3 + 1] = __int_as_float(i1[s]);
                s_top[row * 6 + chalf * 3 + 2] = v2[s];
            }
        }
        if (tid == 0) { s_fq[0] = 0; ((float*)s_fq)[1] = g_mx[qs]; }
        __syncthreads();

        // ---- merge col halves + eps gate ----
        if (tid < TMK) {
            float a1 = s_top[tid * 6 + 0], a2 = s_top[tid * 6 + 2];
            int ai = __float_as_int(s_top[tid * 6 + 1]);
            float b1 = s_top[tid * 6 + 3], b2 = s_top[tid * 6 + 5];
            int bi = __float_as_int(s_top[tid * 6 + 4]);
            float w1; int wi; float rest;
            if (b1 < a1 || (b1 == a1 && bi < ai)) { w1 = b1; wi = bi; rest = a1; }
            else                                   { w1 = a1; wi = ai; rest = b1; }
            float w2 = fminf(rest, fminf(a2, b2));
            const float* rr = s_r + tid * RS;
            float pn = 0.f;
#pragma unroll
            for (int u = 0; u < 16; u++) {
                float4 v = *(const float4*)(rr + (u << 2));
                pn = __fmaf_rn(v.x, v.x, pn); pn = __fmaf_rn(v.y, v.y, pn);
                pn = __fmaf_rn(v.z, v.z, pn); pn = __fmaf_rn(v.w, v.w, pn);
            }
            float mx = ((float*)s_fq)[1];
            float eps = EPSC * __fsqrt_rn(pn * mx) + EPSA;
            if (w2 - w1 > eps) {
                s_idx[tid] = wi;
            } else {
                int p = atomicAdd(&s_fq[0], 1);
                s_fq[2 + p] = tid;
            }
        }
        __syncthreads();

        // ---- slow path: exact fp32 full-row scan (bit-exact ref order) ----
        {
            int nflag = s_fq[0];
            for (int i = wid; i < nflag; i += 8) {
                int row = s_fq[2 + i];
                float bd = 3.0e38f; int bi_ = 0x7fffffff;
                const float* rrow = s_r + row * RS;
#pragma unroll 1
                for (int j = 0; j < 32; j++) {
                    int col = lane + (j << 5);
                    const float4* cp = (const float4*)(cbq + (size_t)col * DDIM);
                    float acc = 0.f;
#pragma unroll
                    for (int u = 0; u < 16; u++) {
                        float4 cv = cp[u];
                        const float* rv = rrow + (u << 2);
                        acc = __fmaf_rn(rv[0], cv.x, acc);
                        acc = __fmaf_rn(rv[1], cv.y, acc);
                        acc = __fmaf_rn(rv[2], cv.z, acc);
                        acc = __fmaf_rn(rv[3], cv.w, acc);
                    }
                    float dv = __fmaf_rn(-2.0f, acc, s_hn[col]);
                    if (dv < bd) { bd = dv; bi_ = col; }
                }
#pragma unroll
                for (int off = 16; off > 0; off >>= 1) {
                    float ov = __shfl_xor_sync(0xffffffffu, bd, off);
                    int oi = __shfl_xor_sync(0xffffffffu, bi_, off);
                    if (ov < bd || (ov == bd && oi < bi_)) { bd = ov; bi_ = oi; }
                }
                if (lane == 0) s_idx[row] = bi_;
            }
        }
        __syncthreads();

        // ---- enc write + q/r update (bit-exact, validated) ----
        if (tid < TMK) {
            int id = s_idx[tid];
            size_t e = (size_t)(row_base + tid) * QSTAGES + qs;
            if (enc_f) enc_f[e] = (float)id;
            if (enc_i) enc_i[e] = id;
        }
        {
            int row = tid >> 1, dh = (tid & 1) << 5;
            int id = s_idx[row];
            const float4* cp = (const float4*)(cbq + (size_t)id * DDIM + dh);
            const float4* xp = (const float4*)(x + (size_t)(row_base + row) * DDIM + dh);
            float* qrow = qbuf + (size_t)(row_base + row) * DDIM + dh;
#pragma unroll
            for (int j = 0; j < 8; j++) {
                float4 cv = cp[j];
                float4 xv = xp[j];
                float4 qv;
                if (qs == 0) { qv.x = qv.y = qv.z = qv.w = 0.f; }
                else qv = *(const float4*)(qrow + (j << 2));
                float q0 = qv.x + cv.x, q1 = qv.y + cv.y;
                float q2 = qv.z + cv.z, q3 = qv.w + cv.w;
                float4 qo; qo.x = q0; qo.y = q1; qo.z = q2; qo.w = q3;
                *(float4*)(qrow + (j << 2)) = qo;
                float4 ro;
                ro.x = xv.x - q0; ro.y = xv.y - q1;
                ro.z = xv.z - q2; ro.w = xv.w - q3;
                *(float4*)(s_r + row * RS + dh + (j << 2)) = ro;
            }
        }
        __syncthreads();
    }
}

// ---------------- launch ----------------
extern "C" void kernel_launch(void* const* d_in, const int* in_sizes, int n_in,
                              void* d_out, int out_size) {
    const float* x = (const float*)d_in[0];
    const float* cb = (const float*)d_in[1];
    if (n_in >= 2 && in_sizes[0] == QSTAGES * KCODES * DDIM &&
        in_sizes[1] == N_ROWS * DDIM) {
        x = (const float*)d_in[1];
        cb = (const float*)d_in[0];
    }

    cudaFuncSetAttribute(rvq_mma_kernel,
                         cudaFuncAttributeMaxDynamicSharedMemorySize, SMEM_BYTES);

    hn_kernel<<<(QSTAGES * KCODES * 32 + 255) / 256, 256>>>(cb);
    mx_kernel<<<QSTAGES, 256>>>();
    split_kernel<<<(QSTAGES * KCODES + 255) / 256, 256>>>(cb);

    const long long enc_n = (long long)N_ROWS * QSTAGES;
    const long long qz_n = (long long)N_ROWS * DDIM;

    float* qz = nullptr;
    float* enc_f = nullptr;
    int* enc_i = nullptr;
    if ((long long)out_size == enc_n + qz_n) {
        enc_f = (float*)d_out;
        qz = (float*)d_out + enc_n;
    } else if ((long long)out_size == qz_n) {
        qz = (float*)d_out;
    } else if ((long long)out_size == enc_n) {
        enc_i = (int*)d_out;
    } else {
        enc_f = (float*)d_out;
        if ((long long)out_size >= enc_n + qz_n) qz = (float*)d_out + enc_n;
    }

    float* qbuf = qz;
    if (!qbuf) cudaGetSymbolAddress((void**)&qbuf, g_qscratch);

    rvq_mma_kernel<<<N_ROWS / TMK, NTHREADS, SMEM_BYTES>>>(x, cb, qbuf,
                                                           enc_f, enc_i);
}

// round 15
// speedup vs baseline: 2.0249x; 1.0071x over previous
#include <cuda_runtime.h>
#include <cuda_bf16.h>
#include <cstdint>
#include <cstddef>

#define N_ROWS   262144
#define DDIM     64
#define QSTAGES  8
#define KCODES   1024
#define TMK      128
#define NCH      128            // cols per chunk
#define NCHUNKS  (KCODES / NCH)
#define NTHREADS 256
#define RS       68             // s_r row stride (fp32) — multiple of 4!
#define SB       72             // B smem row stride (bf16) -> 144B rows

#define EPSC 3e-4f
#define EPSA 1e-5f

// ---- smem layout (float units) ----
// TOP/IDX/FQ alias B buffer 1 (lifetimes disjoint: written after the chunk
// loop's last sync, consumed before next stage's c=0 staging of buf 1).
#define OFF_R        0                        // 128*68 = 8704 fp32
#define OFF_B        8704                     // 2 bufs x 9216 fp32
#define BBUF_FLOATS  9216                     // one buf: hi 18432B + lo 18432B
#define OFF_TOP      (OFF_B + BBUF_FLOATS)    // 17920 (aliases buf 1): 768
#define OFF_IDX      (OFF_TOP + 768)          // 18688: 128 ints
#define OFF_FQ       (OFF_IDX + 128)          // 18816: cnt, mx, queue[128]
#define OFF_HN       (OFF_B + 2 * BBUF_FLOATS) // 27136
#define SMEM_FLOATS  (OFF_HN + KCODES)        // 28160
#define SMEM_BYTES   (SMEM_FLOATS * 4)        // 112,640 B (x2 CTAs = 225,280)

#define BBUF_BYTES 36864
#define BLO_OFF    18432

__device__ float g_hn[QSTAGES * KCODES];
__device__ float g_mx[QSTAGES];
__device__ __nv_bfloat16 g_cbh[QSTAGES * KCODES * DDIM];
__device__ __nv_bfloat16 g_cbl[QSTAGES * KCODES * DDIM];
__device__ float g_qscratch[(size_t)N_ROWS * DDIM];

// ================= asm helpers (baseline PTX only) =================
__device__ __forceinline__ uint32_t smem_u32_of(const void* p) {
    uint32_t a;
    asm("{ .reg .u64 t; cvta.to.shared.u64 t, %1; cvt.u32.u64 %0, t; }"
        : "=r"(a) : "l"(p));
    return a;
}
__device__ __forceinline__ void ldsm_x4(uint32_t& r0, uint32_t& r1,
                                        uint32_t& r2, uint32_t& r3,
                                        uint32_t addr) {
    asm volatile("ldmatrix.sync.aligned.m8n8.x4.shared.b16 {%0,%1,%2,%3}, [%4];"
                 : "=r"(r0), "=r"(r1), "=r"(r2), "=r"(r3) : "r"(addr));
}
__device__ __forceinline__ void mma_bf16(float* d, const uint32_t* a,
                                         uint32_t b0, uint32_t b1) {
    asm volatile(
        "mma.sync.aligned.m16n8k16.row.col.f32.bf16.bf16.f32 "
        "{%0,%1,%2,%3}, {%4,%5,%6,%7}, {%8,%9}, {%0,%1,%2,%3};"
        : "+f"(d[0]), "+f"(d[1]), "+f"(d[2]), "+f"(d[3])
        : "r"(a[0]), "r"(a[1]), "r"(a[2]), "r"(a[3]), "r"(b0), "r"(b1));
}
__device__ __forceinline__ void cp16(uint32_t dst, const void* src) {
    asm volatile("cp.async.cg.shared.global [%0], [%1], 16;"
                 :: "r"(dst), "l"(src) : "memory");
}
#define CP_COMMIT() asm volatile("cp.async.commit_group;" ::: "memory")
#define CP_WAIT0()  asm volatile("cp.async.wait_group 0;" ::: "memory")
#define CP_WAIT1()  asm volatile("cp.async.wait_group 1;" ::: "memory")

__device__ __forceinline__ uint32_t pack_split(float f0, float f1,
                                               uint32_t& lo) {
    __nv_bfloat16 h0 = __float2bfloat16_rn(f0);
    __nv_bfloat16 h1 = __float2bfloat16_rn(f1);
    __nv_bfloat16 g0 = __float2bfloat16_rn(f0 - __bfloat162float(h0));
    __nv_bfloat16 g1 = __float2bfloat16_rn(f1 - __bfloat162float(h1));
    lo = (uint32_t)__bfloat16_as_ushort(g0) |
         ((uint32_t)__bfloat16_as_ushort(g1) << 16);
    return (uint32_t)__bfloat16_as_ushort(h0) |
           ((uint32_t)__bfloat16_as_ushort(h1) << 16);
}

// ================= prep kernels =================
__global__ void hn_kernel(const float* __restrict__ cb) {
    int warp = (blockIdx.x * blockDim.x + threadIdx.x) >> 5;
    int lane = threadIdx.x & 31;
    if (warp < QSTAGES * KCODES) {
        const float* row = cb + (size_t)warp * DDIM;
        float c0 = row[lane];
        float c1 = row[lane + 32];
        float acc = __fmaf_rn(c0, c0, 0.0f);
        acc = __fmaf_rn(c1, c1, acc);
#pragma unroll
        for (int off = 16; off > 0; off >>= 1)
            acc = acc + __shfl_down_sync(0xffffffffu, acc, off);
        if (lane == 0) g_hn[warp] = acc;
    }
}
__global__ void mx_kernel() {
    __shared__ float red[256];
    int q = blockIdx.x, tid = threadIdx.x;
    float m = 0.f;
    for (int i = tid; i < KCODES; i += 256) m = fmaxf(m, g_hn[q * KCODES + i]);
    red[tid] = m; __syncthreads();
    for (int s = 128; s > 0; s >>= 1) {
        if (tid < s) red[tid] = fmaxf(red[tid], red[tid + s]);
        __syncthreads();
    }
    if (tid == 0) g_mx[q] = red[0];
}
__global__ void split_kernel(const float* __restrict__ cb) {
    int gid = blockIdx.x * blockDim.x + threadIdx.x;
    if (gid >= QSTAGES * KCODES) return;
    const float* src = cb + (size_t)gid * DDIM;
    __nv_bfloat16* bh = g_cbh + (size_t)gid * DDIM;
    __nv_bfloat16* bl = g_cbl + (size_t)gid * DDIM;
#pragma unroll
    for (int d = 0; d < DDIM; d++) {
        float f = src[d];
        __nv_bfloat16 h = __float2bfloat16_rn(f);
        bh[d] = h;
        bl[d] = __float2bfloat16_rn(f - __bfloat162float(h));
    }
}

// merge top-2 triples: smaller d wins, ties -> lower index
__device__ __forceinline__ void merge2(float& v1, int& i1, float& v2,
                                       float ov1, int oi1, float ov2) {
    if (ov1 < v1 || (ov1 == v1 && oi1 < i1)) {
        v2 = fminf(v1, ov2); v1 = ov1; i1 = oi1;
    } else {
        v2 = fminf(v2, ov1);
    }
}

// pairwise top-2 update: candidates (dv0@c0, dv1@c0+1)
__device__ __forceinline__ void upd_pair(float& v1, int& i1, float& v2,
                                         float dv0, float dv1, int c0) {
    float m = fminf(dv0, dv1);
    float loser = fmaxf(dv0, dv1);
    int im = (dv1 < dv0) ? (c0 + 1) : c0;   // tie -> lower index
    if (m < v1) { v2 = fminf(v1, loser); v1 = m; i1 = im; }
    else        { v2 = fminf(v2, m); }
}

// ================= main kernel =================
__global__ void __launch_bounds__(NTHREADS, 2)
rvq_mma_kernel(const float* __restrict__ x, const float* __restrict__ cb,
               float* __restrict__ qbuf, float* __restrict__ enc_f,
               int* __restrict__ enc_i) {
    extern __shared__ float smem[];
    float* s_r   = smem + OFF_R;
    float* s_hn  = smem + OFF_HN;
    float* s_top = smem + OFF_TOP;
    int*   s_idx = (int*)(smem + OFF_IDX);
    int*   s_fq  = (int*)(smem + OFF_FQ);

    const int tid = threadIdx.x;
    const int wid = tid >> 5;
    const int lane = tid & 31;
    const int g = lane >> 2;          // 0..7
    const int qd = lane & 3;          // 0..3
    const int rhalf = wid & 3;        // row quarter (32 rows)
    const int chalf = wid >> 2;       // col half (64 cols)
    const int row_base = blockIdx.x * TMK;
    const uint32_t sm_b = smem_u32_of(smem) + OFF_B * 4;
    const uint32_t lm_off = ((uint32_t)(lane & 7) * SB + (uint32_t)(lane >> 3) * 8) * 2
                          + (uint32_t)chalf * 64 * SB * 2;

    // ---- init residual = x ----
    {
        int row = tid >> 1, dh = (tid & 1) << 5;
        const float4* xp = (const float4*)(x + (size_t)(row_base + row) * DDIM + dh);
#pragma unroll
        for (int j = 0; j < 8; j++)
            *(float4*)(s_r + row * RS + dh + (j << 2)) = xp[j];
    }

    for (int qs = 0; qs < QSTAGES; qs++) {
        const float* cbq = cb + (size_t)qs * (KCODES * DDIM);
        const __nv_bfloat16* cbh = g_cbh + (size_t)qs * (KCODES * DDIM);
        const __nv_bfloat16* cbl = g_cbl + (size_t)qs * (KCODES * DDIM);

#pragma unroll
        for (int i = 0; i < KCODES / NTHREADS; i++)
            s_hn[tid + i * NTHREADS] = g_hn[qs * KCODES + tid + i * NTHREADS];
        __syncthreads();

        // ---- A fragments (32 rows per warp, 2 rowfrags), bf16 hi/lo ----
        uint32_t ah[2][4][4], al[2][4][4];
        {
            int rlo = rhalf * 32 + g;
#pragma unroll
            for (int rf = 0; rf < 2; rf++)
#pragma unroll
                for (int f = 0; f < 4; f++)
#pragma unroll
                    for (int p = 0; p < 4; p++) {
                        int row = rlo + rf * 16 + ((p & 1) << 3);
                        int kk = f * 16 + ((p >> 1) << 3) + (qd << 1);
                        float2 v = *(const float2*)(s_r + row * RS + kk);
                        ah[rf][f][p] = pack_split(v.x, v.y, al[rf][f][p]);
                    }
        }

        // ---- stage chunk 0 (cp.async) into buf 0 ----
        {
            uint32_t dsth = sm_b;
#pragma unroll
            for (int t = 0; t < 4; t++) {
                int idx = t * 256 + tid;
                int n = idx >> 3, j = idx & 7;
                uint32_t doff = (uint32_t)n * 144 + (uint32_t)j * 16;
                cp16(dsth + doff, (const char*)(cbh + (size_t)n * DDIM) + j * 16);
                cp16(dsth + BLO_OFF + doff,
                     (const char*)(cbl + (size_t)n * DDIM) + j * 16);
            }
            CP_COMMIT();
        }

        // top-2 state: 4 row slots (rf*2 + (0: row g, 1: row g+8))
        float v1[4], v2[4];
        int i1[4];
#pragma unroll
        for (int s = 0; s < 4; s++) {
            v1[s] = 3.0e38f; v2[s] = 3.0e38f; i1[s] = 0x7fffffff;
        }

        for (int c = 0; c < NCHUNKS; c++) {
            if (c < NCHUNKS - 1) {
                uint32_t dsth = sm_b + (uint32_t)((c + 1) & 1) * BBUF_BYTES;
                const __nv_bfloat16* sh = cbh + (size_t)(c + 1) * NCH * DDIM;
                const __nv_bfloat16* sl = cbl + (size_t)(c + 1) * NCH * DDIM;
#pragma unroll
                for (int t = 0; t < 4; t++) {
                    int idx = t * 256 + tid;
                    int n = idx >> 3, j = idx & 7;
                    uint32_t doff = (uint32_t)n * 144 + (uint32_t)j * 16;
                    cp16(dsth + doff, (const char*)(sh + (size_t)n * DDIM) + j * 16);
                    cp16(dsth + BLO_OFF + doff,
                         (const char*)(sl + (size_t)n * DDIM) + j * 16);
                }
                CP_COMMIT();
                CP_WAIT1();
            } else {
                CP_WAIT0();
            }
            __syncthreads();

            const uint32_t bh_base = sm_b + (uint32_t)(c & 1) * BBUF_BYTES + lm_off;
            const uint32_t bl_base = bh_base + BLO_OFF;

#pragma unroll 1
            for (int nt = 0; nt < 8; nt++) {
                uint32_t ro = (uint32_t)nt * (8 * SB * 2);
                uint32_t bh[8], bl[8];
                ldsm_x4(bh[0], bh[1], bh[2], bh[3], bh_base + ro);
                ldsm_x4(bh[4], bh[5], bh[6], bh[7], bh_base + ro + 64);
                ldsm_x4(bl[0], bl[1], bl[2], bl[3], bl_base + ro);
                ldsm_x4(bl[4], bl[5], bl[6], bl[7], bl_base + ro + 64);

                int cbase = c * NCH + chalf * 64 + nt * 8 + (qd << 1);
                float2 hv = *(const float2*)(s_hn + cbase);

#pragma unroll
                for (int rf = 0; rf < 2; rf++) {
                    // 4 independent accumulator chains (max depth 4),
                    // interleaved so consecutive MMAs never RAW-depend.
                    float d1a[4] = {0.f, 0.f, 0.f, 0.f};
                    float d1b[4] = {0.f, 0.f, 0.f, 0.f};
                    float d2[4]  = {0.f, 0.f, 0.f, 0.f};
                    float d3[4]  = {0.f, 0.f, 0.f, 0.f};
                    mma_bf16(d1a, ah[rf][0], bh[0], bh[1]);
                    mma_bf16(d1b, ah[rf][2], bh[4], bh[5]);
                    mma_bf16(d2,  ah[rf][0], bl[0], bl[1]);
                    mma_bf16(d3,  al[rf][0], bh[0], bh[1]);
                    mma_bf16(d1a, ah[rf][1], bh[2], bh[3]);
                    mma_bf16(d1b, ah[rf][3], bh[6], bh[7]);
                    mma_bf16(d2,  ah[rf][1], bl[2], bl[3]);
                    mma_bf16(d3,  al[rf][1], bh[2], bh[3]);
                    mma_bf16(d2,  ah[rf][2], bl[4], bl[5]);
                    mma_bf16(d3,  al[rf][2], bh[4], bh[5]);
                    mma_bf16(d2,  ah[rf][3], bl[6], bl[7]);
                    mma_bf16(d3,  al[rf][3], bh[6], bh[7]);

                    float s0 = ((d1a[0] + d1b[0]) + d2[0]) + d3[0];
                    float s1 = ((d1a[1] + d1b[1]) + d2[1]) + d3[1];
                    float s2 = ((d1a[2] + d1b[2]) + d2[2]) + d3[2];
                    float s3 = ((d1a[3] + d1b[3]) + d2[3]) + d3[3];
                    float dv0 = __fmaf_rn(-2.0f, s0, hv.x);
                    float dv1 = __fmaf_rn(-2.0f, s1, hv.y);
                    float dv2 = __fmaf_rn(-2.0f, s2, hv.x);
                    float dv3 = __fmaf_rn(-2.0f, s3, hv.y);
                    int s0i = rf * 2;
                    upd_pair(v1[s0i], i1[s0i], v2[s0i], dv0, dv1, cbase);
                    upd_pair(v1[s0i + 1], i1[s0i + 1], v2[s0i + 1], dv2, dv3, cbase);
                }
            }
            __syncthreads();
        }
        // From here, buf 1 region reused for s_top / s_idx / s_fq.

        // ---- quad merge (lanes with same g share rows) ----
#pragma unroll
        for (int s = 0; s < 4; s++) {
#pragma unroll
            for (int off = 1; off <= 2; off <<= 1) {
                float ov1 = __shfl_xor_sync(0xffffffffu, v1[s], off);
                int oi1 = __shfl_xor_sync(0xffffffffu, i1[s], off);
                float ov2 = __shfl_xor_sync(0xffffffffu, v2[s], off);
                merge2(v1[s], i1[s], v2[s], ov1, oi1, ov2);
            }
        }
        if (qd == 0) {
            int rlo = rhalf * 32 + g;
#pragma unroll
            for (int s = 0; s < 4; s++) {
                int row = rlo + ((s & 1) << 3) + ((s >> 1) << 4);
                s_top[row * 6 + chalf * 3 + 0] = v1[s];
                s_top[row * 6 + chalf * 3 + 1] = __int_as_float(i1[s]);
                s_top[row * 6 + chalf * 3 + 2] = v2[s];
            }
        }
        if (tid == 0) { s_fq[0] = 0; ((float*)s_fq)[1] = g_mx[qs]; }
        __syncthreads();

        // ---- merge col halves + eps gate ----
        if (tid < TMK) {
            float a1 = s_top[tid * 6 + 0], a2 = s_top[tid * 6 + 2];
            int ai = __float_as_int(s_top[tid * 6 + 1]);
            float b1 = s_top[tid * 6 + 3], b2 = s_top[tid * 6 + 5];
            int bi = __float_as_int(s_top[tid * 6 + 4]);
            float w1; int wi; float rest;
            if (b1 < a1 || (b1 == a1 && bi < ai)) { w1 = b1; wi = bi; rest = a1; }
            else                                   { w1 = a1; wi = ai; rest = b1; }
            float w2 = fminf(rest, fminf(a2, b2));
            const float* rr = s_r + tid * RS;
            float pn = 0.f;
#pragma unroll
            for (int u = 0; u < 16; u++) {
                float4 v = *(const float4*)(rr + (u << 2));
                pn = __fmaf_rn(v.x, v.x, pn); pn = __fmaf_rn(v.y, v.y, pn);
                pn = __fmaf_rn(v.z, v.z, pn); pn = __fmaf_rn(v.w, v.w, pn);
            }
            float mx = ((float*)s_fq)[1];
            float eps = EPSC * __fsqrt_rn(pn * mx) + EPSA;
            if (w2 - w1 > eps) {
                s_idx[tid] = wi;
            } else {
                int p = atomicAdd(&s_fq[0], 1);
                s_fq[2 + p] = tid;
            }
        }
        __syncthreads();

        // ---- slow path: exact fp32 full-row scan (bit-exact ref order) ----
        {
            int nflag = s_fq[0];
            for (int i = wid; i < nflag; i += 8) {
                int row = s_fq[2 + i];
                float bd = 3.0e38f; int bi_ = 0x7fffffff;
                const float* rrow = s_r + row * RS;
#pragma unroll 1
                for (int j = 0; j < 32; j++) {
                    int col = lane + (j << 5);
                    const float4* cp = (const float4*)(cbq + (size_t)col * DDIM);
                    float acc = 0.f;
#pragma unroll
                    for (int u = 0; u < 16; u++) {
                        float4 cv = cp[u];
                        const float* rv = rrow + (u << 2);
                        acc = __fmaf_rn(rv[0], cv.x, acc);
                        acc = __fmaf_rn(rv[1], cv.y, acc);
                        acc = __fmaf_rn(rv[2], cv.z, acc);
                        acc = __fmaf_rn(rv[3], cv.w, acc);
                    }
                    float dv = __fmaf_rn(-2.0f, acc, s_hn[col]);
                    if (dv < bd) { bd = dv; bi_ = col; }
                }
#pragma unroll
                for (int off = 16; off > 0; off >>= 1) {
                    float ov = __shfl_xor_sync(0xffffffffu, bd, off);
                    int oi = __shfl_xor_sync(0xffffffffu, bi_, off);
                    if (ov < bd || (ov == bd && oi < bi_)) { bd = ov; bi_ = oi; }
                }
                if (lane == 0) s_idx[row] = bi_;
            }
        }
        __syncthreads();

        // ---- enc write + q/r update (bit-exact, validated) ----
        if (tid < TMK) {
            int id = s_idx[tid];
            size_t e = (size_t)(row_base + tid) * QSTAGES + qs;
            if (enc_f) enc_f[e] = (float)id;
            if (enc_i) enc_i[e] = id;
        }
        {
            int row = tid >> 1, dh = (tid & 1) << 5;
            int id = s_idx[row];
            const float4* cp = (const float4*)(cbq + (size_t)id * DDIM + dh);
            const float4* xp = (const float4*)(x + (size_t)(row_base + row) * DDIM + dh);
            float* qrow = qbuf + (size_t)(row_base + row) * DDIM + dh;
#pragma unroll
            for (int j = 0; j < 8; j++) {
                float4 cv = cp[j];
                float4 xv = xp[j];
                float4 qv;
                if (qs == 0) { qv.x = qv.y = qv.z = qv.w = 0.f; }
                else qv = *(const float4*)(qrow + (j << 2));
                float q0 = qv.x + cv.x, q1 = qv.y + cv.y;
                float q2 = qv.z + cv.z, q3 = qv.w + cv.w;
                float4 qo; qo.x = q0; qo.y = q1; qo.z = q2; qo.w = q3;
                *(float4*)(qrow + (j << 2)) = qo;
                float4 ro;
                ro.x = xv.x - q0; ro.y = xv.y - q1;
                ro.z = xv.z - q2; ro.w = xv.w - q3;
                *(float4*)(s_r + row * RS + dh + (j << 2)) = ro;
            }
        }
        __syncthreads();
    }
}

// ---------------- launch ----------------
extern "C" void kernel_launch(void* const* d_in, const int* in_sizes, int n_in,
                              void* d_out, int out_size) {
    const float* x = (const float*)d_in[0];
    const float* cb = (const float*)d_in[1];
    if (n_in >= 2 && in_sizes[0] == QSTAGES * KCODES * DDIM &&
        in_sizes[1] == N_ROWS * DDIM) {
        x = (const float*)d_in[1];
        cb = (const float*)d_in[0];
    }

    cudaFuncSetAttribute(rvq_mma_kernel,
                         cudaFuncAttributeMaxDynamicSharedMemorySize, SMEM_BYTES);

    hn_kernel<<<(QSTAGES * KCODES * 32 + 255) / 256, 256>>>(cb);
    mx_kernel<<<QSTAGES, 256>>>();
    split_kernel<<<(QSTAGES * KCODES + 255) / 256, 256>>>(cb);

    const long long enc_n = (long long)N_ROWS * QSTAGES;
    const long long qz_n = (long long)N_ROWS * DDIM;

    float* qz = nullptr;
    float* enc_f = nullptr;
    int* enc_i = nullptr;
    if ((long long)out_size == enc_n + qz_n) {
        enc_f = (float*)d_out;
        qz = (float*)d_out + enc_n;
    } else if ((long long)out_size == qz_n) {
        qz = (float*)d_out;
    } else if ((long long)out_size == enc_n) {
        enc_i = (int*)d_out;
    } else {
        enc_f = (float*)d_out;
        if ((long long)out_size >= enc_n + qz_n) qz = (float*)d_out + enc_n;
    }

    float* qbuf = qz;
    if (!qbuf) cudaGetSymbolAddress((void**)&qbuf, g_qscratch);

    rvq_mma_kernel<<<N_ROWS / TMK, NTHREADS, SMEM_BYTES>>>(x, cb, qbuf,
                                                           enc_f, enc_i);
}

// round 16
// speedup vs baseline: 2.1586x; 1.0660x over previous
#include <cuda_runtime.h>
#include <cuda_bf16.h>
#include <cstdint>
#include <cstddef>

#define N_ROWS   262144
#define DDIM     64
#define QSTAGES  8
#define KCODES   1024
#define TMK      128
#define NCH      128            // cols per chunk
#define NCHUNKS  (KCODES / NCH)
#define NTHREADS 256
#define RS       68             // s_r row stride (fp32) — multiple of 4!
#define SB       72             // B smem row stride (bf16) -> 144B rows

#define EPSC 3e-4f
#define EPSA 1e-5f

// ---- smem layout (float units) ----
// TOP/IDX/FQ alias B buffer 1 (lifetimes disjoint: written after the chunk
// loop's last sync, consumed before next stage's c=0 staging of buf 1).
#define OFF_R        0                        // 128*68 = 8704 fp32
#define OFF_B        8704                     // 2 bufs x 9216 fp32
#define BBUF_FLOATS  9216                     // one buf: hi 18432B + lo 18432B
#define OFF_TOP      (OFF_B + BBUF_FLOATS)    // 17920 (aliases buf 1): 768
#define OFF_IDX      (OFF_TOP + 768)          // 18688: 128 ints
#define OFF_FQ       (OFF_IDX + 128)          // 18816: cnt, mx, queue[128]
#define OFF_HN       (OFF_B + 2 * BBUF_FLOATS) // 27136
#define SMEM_FLOATS  (OFF_HN + KCODES)        // 28160
#define SMEM_BYTES   (SMEM_FLOATS * 4)        // 112,640 B (x2 CTAs = 225,280)

#define BBUF_BYTES 36864
#define BLO_OFF    18432

__device__ float g_hn[QSTAGES * KCODES];
__device__ float g_mx[QSTAGES];
__device__ __nv_bfloat16 g_cbh[QSTAGES * KCODES * DDIM];
__device__ __nv_bfloat16 g_cbl[QSTAGES * KCODES * DDIM];
__device__ float g_qscratch[(size_t)N_ROWS * DDIM];

// ================= asm helpers (baseline PTX only) =================
__device__ __forceinline__ uint32_t smem_u32_of(const void* p) {
    uint32_t a;
    asm("{ .reg .u64 t; cvta.to.shared.u64 t, %1; cvt.u32.u64 %0, t; }"
        : "=r"(a) : "l"(p));
    return a;
}
__device__ __forceinline__ void ldsm_x4(uint32_t& r0, uint32_t& r1,
                                        uint32_t& r2, uint32_t& r3,
                                        uint32_t addr) {
    asm volatile("ldmatrix.sync.aligned.m8n8.x4.shared.b16 {%0,%1,%2,%3}, [%4];"
                 : "=r"(r0), "=r"(r1), "=r"(r2), "=r"(r3) : "r"(addr));
}
__device__ __forceinline__ void mma_bf16(float* d, const uint32_t* a,
                                         uint32_t b0, uint32_t b1) {
    asm volatile(
        "mma.sync.aligned.m16n8k16.row.col.f32.bf16.bf16.f32 "
        "{%0,%1,%2,%3}, {%4,%5,%6,%7}, {%8,%9}, {%0,%1,%2,%3};"
        : "+f"(d[0]), "+f"(d[1]), "+f"(d[2]), "+f"(d[3])
        : "r"(a[0]), "r"(a[1]), "r"(a[2]), "r"(a[3]), "r"(b0), "r"(b1));
}
__device__ __forceinline__ void cp16(uint32_t dst, const void* src) {
    asm volatile("cp.async.cg.shared.global [%0], [%1], 16;"
                 :: "r"(dst), "l"(src) : "memory");
}
#define CP_COMMIT() asm volatile("cp.async.commit_group;" ::: "memory")
#define CP_WAIT0()  asm volatile("cp.async.wait_group 0;" ::: "memory")
#define CP_WAIT1()  asm volatile("cp.async.wait_group 1;" ::: "memory")

__device__ __forceinline__ uint32_t pack_split(float f0, float f1,
                                               uint32_t& lo) {
    __nv_bfloat16 h0 = __float2bfloat16_rn(f0);
    __nv_bfloat16 h1 = __float2bfloat16_rn(f1);
    __nv_bfloat16 g0 = __float2bfloat16_rn(f0 - __bfloat162float(h0));
    __nv_bfloat16 g1 = __float2bfloat16_rn(f1 - __bfloat162float(h1));
    lo = (uint32_t)__bfloat16_as_ushort(g0) |
         ((uint32_t)__bfloat16_as_ushort(g1) << 16);
    return (uint32_t)__bfloat16_as_ushort(h0) |
           ((uint32_t)__bfloat16_as_ushort(h1) << 16);
}

// ================= prep kernels =================
__global__ void hn_kernel(const float* __restrict__ cb) {
    int warp = (blockIdx.x * blockDim.x + threadIdx.x) >> 5;
    int lane = threadIdx.x & 31;
    if (warp < QSTAGES * KCODES) {
        const float* row = cb + (size_t)warp * DDIM;
        float c0 = row[lane];
        float c1 = row[lane + 32];
        float acc = __fmaf_rn(c0, c0, 0.0f);
        acc = __fmaf_rn(c1, c1, acc);
#pragma unroll
        for (int off = 16; off > 0; off >>= 1)
            acc = acc + __shfl_down_sync(0xffffffffu, acc, off);
        if (lane == 0) g_hn[warp] = acc;
    }
}
__global__ void mx_kernel() {
    __shared__ float red[256];
    int q = blockIdx.x, tid = threadIdx.x;
    float m = 0.f;
    for (int i = tid; i < KCODES; i += 256) m = fmaxf(m, g_hn[q * KCODES + i]);
    red[tid] = m; __syncthreads();
    for (int s = 128; s > 0; s >>= 1) {
        if (tid < s) red[tid] = fmaxf(red[tid], red[tid + s]);
        __syncthreads();
    }
    if (tid == 0) g_mx[q] = red[0];
}
__global__ void split_kernel(const float* __restrict__ cb) {
    int gid = blockIdx.x * blockDim.x + threadIdx.x;
    if (gid >= QSTAGES * KCODES) return;
    const float* src = cb + (size_t)gid * DDIM;
    __nv_bfloat16* bh = g_cbh + (size_t)gid * DDIM;
    __nv_bfloat16* bl = g_cbl + (size_t)gid * DDIM;
#pragma unroll
    for (int d = 0; d < DDIM; d++) {
        float f = src[d];
        __nv_bfloat16 h = __float2bfloat16_rn(f);
        bh[d] = h;
        bl[d] = __float2bfloat16_rn(f - __bfloat162float(h));
    }
}

// merge top-2 triples: smaller d wins, ties -> lower index
__device__ __forceinline__ void merge2(float& v1, int& i1, float& v2,
                                       float ov1, int oi1, float ov2) {
    if (ov1 < v1 || (ov1 == v1 && oi1 < i1)) {
        v2 = fminf(v1, ov2); v1 = ov1; i1 = oi1;
    } else {
        v2 = fminf(v2, ov1);
    }
}

// pairwise top-2 update: candidates (dv0@c0, dv1@c0+1)
__device__ __forceinline__ void upd_pair(float& v1, int& i1, float& v2,
                                         float dv0, float dv1, int c0) {
    float m = fminf(dv0, dv1);
    float loser = fmaxf(dv0, dv1);
    int im = (dv1 < dv0) ? (c0 + 1) : c0;   // tie -> lower index
    if (m < v1) { v2 = fminf(v1, loser); v1 = m; i1 = im; }
    else        { v2 = fminf(v2, m); }
}

// ================= main kernel =================
__global__ void __launch_bounds__(NTHREADS, 2)
rvq_mma_kernel(const float* __restrict__ x, const float* __restrict__ cb,
               float* __restrict__ qbuf, float* __restrict__ enc_f,
               int* __restrict__ enc_i) {
    extern __shared__ float smem[];
    float* s_r   = smem + OFF_R;
    float* s_hn  = smem + OFF_HN;
    float* s_top = smem + OFF_TOP;
    int*   s_idx = (int*)(smem + OFF_IDX);
    int*   s_fq  = (int*)(smem + OFF_FQ);

    const int tid = threadIdx.x;
    const int wid = tid >> 5;
    const int lane = tid & 31;
    const int g = lane >> 2;          // 0..7
    const int qd = lane & 3;          // 0..3
    const int rhalf = wid & 3;        // row quarter (32 rows)
    const int chalf = wid >> 2;       // col half (64 cols)
    const int row_base = blockIdx.x * TMK;
    const uint32_t sm_b = smem_u32_of(smem) + OFF_B * 4;
    const uint32_t lm_off = ((uint32_t)(lane & 7) * SB + (uint32_t)(lane >> 3) * 8) * 2
                          + (uint32_t)chalf * 64 * SB * 2;

    // ---- init residual = x ----
    {
        int row = tid >> 1, dh = (tid & 1) << 5;
        const float4* xp = (const float4*)(x + (size_t)(row_base + row) * DDIM + dh);
#pragma unroll
        for (int j = 0; j < 8; j++)
            *(float4*)(s_r + row * RS + dh + (j << 2)) = xp[j];
    }

    for (int qs = 0; qs < QSTAGES; qs++) {
        const float* cbq = cb + (size_t)qs * (KCODES * DDIM);
        const __nv_bfloat16* cbh = g_cbh + (size_t)qs * (KCODES * DDIM);
        const __nv_bfloat16* cbl = g_cbl + (size_t)qs * (KCODES * DDIM);

#pragma unroll
        for (int i = 0; i < KCODES / NTHREADS; i++)
            s_hn[tid + i * NTHREADS] = g_hn[qs * KCODES + tid + i * NTHREADS];
        __syncthreads();

        // ---- A fragments (32 rows per warp, 2 rowfrags), bf16 hi/lo ----
        uint32_t ah[2][4][4], al[2][4][4];
        {
            int rlo = rhalf * 32 + g;
#pragma unroll
            for (int rf = 0; rf < 2; rf++)
#pragma unroll
                for (int f = 0; f < 4; f++)
#pragma unroll
                    for (int p = 0; p < 4; p++) {
                        int row = rlo + rf * 16 + ((p & 1) << 3);
                        int kk = f * 16 + ((p >> 1) << 3) + (qd << 1);
                        float2 v = *(const float2*)(s_r + row * RS + kk);
                        ah[rf][f][p] = pack_split(v.x, v.y, al[rf][f][p]);
                    }
        }

        // ---- stage chunk 0 (cp.async) into buf 0 ----
        {
            uint32_t dsth = sm_b;
#pragma unroll
            for (int t = 0; t < 4; t++) {
                int idx = t * 256 + tid;
                int n = idx >> 3, j = idx & 7;
                uint32_t doff = (uint32_t)n * 144 + (uint32_t)j * 16;
                cp16(dsth + doff, (const char*)(cbh + (size_t)n * DDIM) + j * 16);
                cp16(dsth + BLO_OFF + doff,
                     (const char*)(cbl + (size_t)n * DDIM) + j * 16);
            }
            CP_COMMIT();
        }

        // top-2 state: 4 row slots (rf*2 + (0: row g, 1: row g+8))
        float v1[4], v2[4];
        int i1[4];
#pragma unroll
        for (int s = 0; s < 4; s++) {
            v1[s] = 3.0e38f; v2[s] = 3.0e38f; i1[s] = 0x7fffffff;
        }

        for (int c = 0; c < NCHUNKS; c++) {
            if (c < NCHUNKS - 1) {
                uint32_t dsth = sm_b + (uint32_t)((c + 1) & 1) * BBUF_BYTES;
                const __nv_bfloat16* sh = cbh + (size_t)(c + 1) * NCH * DDIM;
                const __nv_bfloat16* sl = cbl + (size_t)(c + 1) * NCH * DDIM;
#pragma unroll
                for (int t = 0; t < 4; t++) {
                    int idx = t * 256 + tid;
                    int n = idx >> 3, j = idx & 7;
                    uint32_t doff = (uint32_t)n * 144 + (uint32_t)j * 16;
                    cp16(dsth + doff, (const char*)(sh + (size_t)n * DDIM) + j * 16);
                    cp16(dsth + BLO_OFF + doff,
                         (const char*)(sl + (size_t)n * DDIM) + j * 16);
                }
                CP_COMMIT();
                CP_WAIT1();
            } else {
                CP_WAIT0();
            }
            __syncthreads();

            const uint32_t bh_base = sm_b + (uint32_t)(c & 1) * BBUF_BYTES + lm_off;
            const uint32_t bl_base = bh_base + BLO_OFF;

#pragma unroll 2
            for (int nt = 0; nt < 8; nt++) {
                uint32_t ro = (uint32_t)nt * (8 * SB * 2);
                uint32_t bh[8], bl[8];
                ldsm_x4(bh[0], bh[1], bh[2], bh[3], bh_base + ro);
                ldsm_x4(bh[4], bh[5], bh[6], bh[7], bh_base + ro + 64);
                ldsm_x4(bl[0], bl[1], bl[2], bl[3], bl_base + ro);
                ldsm_x4(bl[4], bl[5], bl[6], bl[7], bl_base + ro + 64);

                int cbase = c * NCH + chalf * 64 + nt * 8 + (qd << 1);
                float2 hv = *(const float2*)(s_hn + cbase);

#pragma unroll
                for (int rf = 0; rf < 2; rf++) {
                    // single fused accumulator: all 3 passes chain into d
                    // (MMA accumulates; no scalar sum-adds needed)
                    float d[4] = {0.f, 0.f, 0.f, 0.f};
#pragma unroll
                    for (int f = 0; f < 4; f++)
                        mma_bf16(d, ah[rf][f], bh[2 * f], bh[2 * f + 1]);
#pragma unroll
                    for (int f = 0; f < 4; f++)
                        mma_bf16(d, ah[rf][f], bl[2 * f], bl[2 * f + 1]);
#pragma unroll
                    for (int f = 0; f < 4; f++)
                        mma_bf16(d, al[rf][f], bh[2 * f], bh[2 * f + 1]);

                    float dv0 = __fmaf_rn(-2.0f, d[0], hv.x);
                    float dv1 = __fmaf_rn(-2.0f, d[1], hv.y);
                    float dv2 = __fmaf_rn(-2.0f, d[2], hv.x);
                    float dv3 = __fmaf_rn(-2.0f, d[3], hv.y);
                    int s0i = rf * 2;
                    upd_pair(v1[s0i], i1[s0i], v2[s0i], dv0, dv1, cbase);
                    upd_pair(v1[s0i + 1], i1[s0i + 1], v2[s0i + 1], dv2, dv3, cbase);
                }
            }
            __syncthreads();
        }
        // From here, buf 1 region reused for s_top / s_idx / s_fq.

        // ---- quad merge (lanes with same g share rows) ----
#pragma unroll
        for (int s = 0; s < 4; s++) {
#pragma unroll
            for (int off = 1; off <= 2; off <<= 1) {
                float ov1 = __shfl_xor_sync(0xffffffffu, v1[s], off);
                int oi1 = __shfl_xor_sync(0xffffffffu, i1[s], off);
                float ov2 = __shfl_xor_sync(0xffffffffu, v2[s], off);
                merge2(v1[s], i1[s], v2[s], ov1, oi1, ov2);
            }
        }
        if (qd == 0) {
            int rlo = rhalf * 32 + g;
#pragma unroll
            for (int s = 0; s < 4; s++) {
                int row = rlo + ((s & 1) << 3) + ((s >> 1) << 4);
                s_top[row * 6 + chalf * 3 + 0] = v1[s];
                s_top[row * 6 + chalf * 3 + 1] = __int_as_float(i1[s]);
                s_top[row * 6 + chalf * 3 + 2] = v2[s];
            }
        }
        if (tid == 0) { s_fq[0] = 0; ((float*)s_fq)[1] = g_mx[qs]; }
        __syncthreads();

        // ---- merge col halves + eps gate ----
        if (tid < TMK) {
            float a1 = s_top[tid * 6 + 0], a2 = s_top[tid * 6 + 2];
            int ai = __float_as_int(s_top[tid * 6 + 1]);
            float b1 = s_top[tid * 6 + 3], b2 = s_top[tid * 6 + 5];
            int bi = __float_as_int(s_top[tid * 6 + 4]);
            float w1; int wi; float rest;
            if (b1 < a1 || (b1 == a1 && bi < ai)) { w1 = b1; wi = bi; rest = a1; }
            else                                   { w1 = a1; wi = ai; rest = b1; }
            float w2 = fminf(rest, fminf(a2, b2));
            const float* rr = s_r + tid * RS;
            float pn = 0.f;
#pragma unroll
            for (int u = 0; u < 16; u++) {
                float4 v = *(const float4*)(rr + (u << 2));
                pn = __fmaf_rn(v.x, v.x, pn); pn = __fmaf_rn(v.y, v.y, pn);
                pn = __fmaf_rn(v.z, v.z, pn); pn = __fmaf_rn(v.w, v.w, pn);
            }
            float mx = ((float*)s_fq)[1];
            float eps = EPSC * __fsqrt_rn(pn * mx) + EPSA;
            if (w2 - w1 > eps) {
                s_idx[tid] = wi;
            } else {
                int p = atomicAdd(&s_fq[0], 1);
                s_fq[2 + p] = tid;
            }
        }
        __syncthreads();

        // ---- slow path: exact fp32 full-row scan (bit-exact ref order) ----
        {
            int nflag = s_fq[0];
            for (int i = wid; i < nflag; i += 8) {
                int row = s_fq[2 + i];
                float bd = 3.0e38f; int bi_ = 0x7fffffff;
                const float* rrow = s_r + row * RS;
#pragma unroll 1
                for (int j = 0; j < 32; j++) {
                    int col = lane + (j << 5);
                    const float4* cp = (const float4*)(cbq + (size_t)col * DDIM);
                    float acc = 0.f;
#pragma unroll
                    for (int u = 0; u < 16; u++) {
                        float4 cv = cp[u];
                        const float* rv = rrow + (u << 2);
                        acc = __fmaf_rn(rv[0], cv.x, acc);
                        acc = __fmaf_rn(rv[1], cv.y, acc);
                        acc = __fmaf_rn(rv[2], cv.z, acc);
                        acc = __fmaf_rn(rv[3], cv.w, acc);
                    }
                    float dv = __fmaf_rn(-2.0f, acc, s_hn[col]);
                    if (dv < bd) { bd = dv; bi_ = col; }
                }
#pragma unroll
                for (int off = 16; off > 0; off >>= 1) {
                    float ov = __shfl_xor_sync(0xffffffffu, bd, off);
                    int oi = __shfl_xor_sync(0xffffffffu, bi_, off);
                    if (ov < bd || (ov == bd && oi < bi_)) { bd = ov; bi_ = oi; }
                }
                if (lane == 0) s_idx[row] = bi_;
            }
        }
        __syncthreads();

        // ---- enc write + q/r update (bit-exact, validated) ----
        if (tid < TMK) {
            int id = s_idx[tid];
            size_t e = (size_t)(row_base + tid) * QSTAGES + qs;
            if (enc_f) enc_f[e] = (float)id;
            if (enc_i) enc_i[e] = id;
        }
        {
            int row = tid >> 1, dh = (tid & 1) << 5;
            int id = s_idx[row];
            const float4* cp = (const float4*)(cbq + (size_t)id * DDIM + dh);
            const float4* xp = (const float4*)(x + (size_t)(row_base + row) * DDIM + dh);
            float* qrow = qbuf + (size_t)(row_base + row) * DDIM + dh;
#pragma unroll
            for (int j = 0; j < 8; j++) {
                float4 cv = cp[j];
                float4 xv = xp[j];
                float4 qv;
                if (qs == 0) { qv.x = qv.y = qv.z = qv.w = 0.f; }
                else qv = *(const float4*)(qrow + (j << 2));
                float q0 = qv.x + cv.x, q1 = qv.y + cv.y;
                float q2 = qv.z + cv.z, q3 = qv.w + cv.w;
                float4 qo; qo.x = q0; qo.y = q1; qo.z = q2; qo.w = q3;
                *(float4*)(qrow + (j << 2)) = qo;
                float4 ro;
                ro.x = xv.x - q0; ro.y = xv.y - q1;
                ro.z = xv.z - q2; ro.w = xv.w - q3;
                *(float4*)(s_r + row * RS + dh + (j << 2)) = ro;
            }
        }
        __syncthreads();
    }
}

// ---------------- launch ----------------
extern "C" void kernel_launch(void* const* d_in, const int* in_sizes, int n_in,
                              void* d_out, int out_size) {
    const float* x = (const float*)d_in[0];
    const float* cb = (const float*)d_in[1];
    if (n_in >= 2 && in_sizes[0] == QSTAGES * KCODES * DDIM &&
        in_sizes[1] == N_ROWS * DDIM) {
        x = (const float*)d_in[1];
        cb = (const float*)d_in[0];
    }

    cudaFuncSetAttribute(rvq_mma_kernel,
                         cudaFuncAttributeMaxDynamicSharedMemorySize, SMEM_BYTES);

    hn_kernel<<<(QSTAGES * KCODES * 32 + 255) / 256, 256>>>(cb);
    mx_kernel<<<QSTAGES, 256>>>();
    split_kernel<<<(QSTAGES * KCODES + 255) / 256, 256>>>(cb);

    const long long enc_n = (long long)N_ROWS * QSTAGES;
    const long long qz_n = (long long)N_ROWS * DDIM;

    float* qz = nullptr;
    float* enc_f = nullptr;
    int* enc_i = nullptr;
    if ((long long)out_size == enc_n + qz_n) {
        enc_f = (float*)d_out;
        qz = (float*)d_out + enc_n;
    } else if ((long long)out_size == qz_n) {
        qz = (float*)d_out;
    } else if ((long long)out_size == enc_n) {
        enc_i = (int*)d_out;
    } else {
        enc_f = (float*)d_out;
        if ((long long)out_size >= enc_n + qz_n) qz = (float*)d_out + enc_n;
    }

    float* qbuf = qz;
    if (!qbuf) cudaGetSymbolAddress((void**)&qbuf, g_qscratch);

    rvq_mma_kernel<<<N_ROWS / TMK, NTHREADS, SMEM_BYTES>>>(x, cb, qbuf,
                                                           enc_f, enc_i);
}